// round 11
// baseline (speedup 1.0000x reference)
#include <cuda_runtime.h>
#include <cuda_fp16.h>
#include <cstdint>

// ---------------- problem constants ----------------
#define CIN    256
#define COUT   256
#define HDIM   64
#define WDIM   64
#define BATCH  4
#define K2     9
#define HW     4096
#define M_GEMM 2304          // K2 * COUT
#define K_GEMM 256           // CIN

// ---------------- GEMM tiling ----------------
#define BM 128                         // n-tile rows
#define BN 128                         // m-tile cols
#define BK 64                          // fp16 elements per chunk (128B rows)
#define NCHUNK (K_GEMM / BK)           // 4
#define TILE_B (BM * BK * 2)           // 16384 bytes per operand tile
#define STAGE_B (2 * TILE_B)           // A, B = 32 KB
#define SMEM_DYN (2 * STAGE_B)         // 64 KB

#define GEMM_BLOCKS ((HW / BM) * (M_GEMM / BN))   // 32*18 = 576
#define PPB 8
#define COMB_BLOCKS (HW / PPB)                    // 512
#define NCTAS 296                                  // 148 SMs x 2 CTAs, co-resident

// ---------------- scratch (device globals) ----------------
__device__ __half g_Wh[M_GEMM * K_GEMM];      // [m][c]
__device__ __half g_Xh[BATCH * HW * CIN];     // [b][n][c]
// layout: G[b][k][n][o]  (o contiguous), fp16.  75.5 MB
__device__ __half g_Gh[(size_t)BATCH * K2 * HW * COUT];

// grid barrier state: g_cnt returns to 0 after each use; g_gen is monotonic
__device__ unsigned g_cnt = 0;
__device__ unsigned g_gen = 0;

// ---------------- PTX helpers ----------------
__device__ __forceinline__ uint32_t smem_u32(const void* p) {
    uint32_t a;
    asm("{ .reg .u64 t; cvta.to.shared.u64 t, %1; cvt.u32.u64 %0, t; }" : "=r"(a) : "l"(p));
    return a;
}
#define CP16(dst, src)  asm volatile("cp.async.cg.shared.global [%0], [%1], 16;" :: "r"(dst), "l"(src) : "memory")
#define CP_COMMIT()     asm volatile("cp.async.commit_group;" ::: "memory")
#define CP_WAIT(n)      asm volatile("cp.async.wait_group %0;" :: "n"(n) : "memory")

__device__ __forceinline__ void ldsm_x4(uint32_t* r, uint32_t addr) {
    asm volatile("ldmatrix.sync.aligned.m8n8.x4.shared.b16 {%0,%1,%2,%3}, [%4];"
                 : "=r"(r[0]), "=r"(r[1]), "=r"(r[2]), "=r"(r[3]) : "r"(addr));
}
__device__ __forceinline__ void mma_fp16(float* d, const uint32_t* a, const uint32_t* b) {
    asm volatile("mma.sync.aligned.m16n8k16.row.col.f32.f16.f16.f32 "
                 "{%0,%1,%2,%3}, {%4,%5,%6,%7}, {%8,%9}, {%0,%1,%2,%3};"
                 : "+f"(d[0]), "+f"(d[1]), "+f"(d[2]), "+f"(d[3])
                 : "r"(a[0]), "r"(a[1]), "r"(a[2]), "r"(a[3]), "r"(b[0]), "r"(b[1]));
}
__device__ __forceinline__ uint32_t swz(uint32_t off) { return off ^ ((off >> 3) & 0x70); }

// ---------------------------------------------------------------------------
// Grid barrier (all NCTAS co-resident). Generation-based; replay-safe.
// ---------------------------------------------------------------------------
__device__ __forceinline__ void grid_barrier(unsigned target) {
    __syncthreads();
    if (threadIdx.x == 0) {
        __threadfence();                       // publish this CTA's writes
        unsigned old = atomicAdd(&g_cnt, 1u);
        if (old == NCTAS - 1) {
            *(volatile unsigned*)&g_cnt = 0;   // reset for next barrier
            __threadfence();
            atomicAdd(&g_gen, 1u);             // release everyone
        } else {
            while ((int)(*(volatile unsigned*)&g_gen - target) < 0)
                __nanosleep(64);
        }
        __threadfence();                       // acquire
    }
    __syncthreads();
}

// ---------------------------------------------------------------------------
// Kernel 1: blend (blocks 0..255) ∥ transpose all batches (blocks 256..4351)
// ---------------------------------------------------------------------------
__global__ __launch_bounds__(256) void pre_kernel(const float* __restrict__ weight,
                                                  const float* __restrict__ X) {
    const int tid = threadIdx.x;
    if (blockIdx.x < 256) {
        // ---- circle-blend weights -> fp16, K-major [m][c] ----
        int t = blockIdx.x * 256 + tid;
        int o = t >> 8;
        int c = t & 255;
        const float* wp = weight + ((size_t)(o * CIN + c)) * K2;
        float w0 = wp[0], w1 = wp[1], w2 = wp[2];
        float w3 = wp[3], w4 = wp[4], w5 = wp[5];
        float w6 = wp[6], w7 = wp[7], w8 = wp[8];

        const float A  = 0.7071067811865476f;
        const float Bc = 1.0f - 0.7071067811865476f;

        float t01 = A * w0 + Bc * w1;
        float t34 = A * w3 + Bc * w4;
        float t12 = Bc * w1 + A * w2;
        float t45 = Bc * w4 + A * w5;
        float t67 = A * w6 + Bc * w7;
        float t78 = Bc * w7 + A * w8;

        float nw[K2];
        nw[0] = A * t01 + Bc * t34;  nw[1] = w1;
        nw[2] = A * t12 + Bc * t45;  nw[3] = w3;  nw[4] = w4;  nw[5] = w5;
        nw[6] = Bc * t34 + A * t67;  nw[7] = w7;
        nw[8] = Bc * t45 + A * t78;

#pragma unroll
        for (int k = 0; k < K2; k++)
            g_Wh[(size_t)(k * COUT + o) * K_GEMM + c] = __float2half_rn(nw[k]);
    } else {
        // ---- transpose x[b][c][n] -> Xt[b][n][c] in fp16 ----
        __shared__ float tle[32][33];
        int u  = blockIdx.x - 256;       // 0..4095
        int b  = u >> 10;                // 4 batches
        int r  = u & 1023;               // 1024 tiles per batch
        int n0 = (r & 127) * 32;
        int c0 = (r >> 7) * 32;
        int tx = tid & 31, ty = tid >> 5;

        const float* src = X + ((size_t)b * CIN + c0) * HW + n0;
#pragma unroll
        for (int i = ty; i < 32; i += 8)
            tle[i][tx] = src[(size_t)i * HW + tx];
        __syncthreads();

        __half* dh = g_Xh + ((size_t)b * HW + n0) * CIN + c0;
#pragma unroll
        for (int i = ty; i < 32; i += 8)
            dh[(size_t)i * CIN + tx] = __float2half_rn(tle[tx][i]);
    }
}

// ---------------------------------------------------------------------------
// GEMM body: fp16 single-pass, one 128x128 tile
//   G[b][k][n][o] = sum_c Xh[b][n][c] * Wh[k*256+o][c]   (stored fp16)
// ---------------------------------------------------------------------------
extern __shared__ __align__(1024) unsigned char dsmem[];

__device__ void gemm_body(int b, int blk) {
    const int tid  = threadIdx.x;
    const int wid  = tid >> 5;
    const int lane = tid & 31;
    const int warp_m = wid >> 2;       // 0..1  (64 n-rows each)
    const int warp_n = wid & 3;        // 0..3  (32 m-cols each)

    const int n0 = (blk & 31) * BM;    // n tile (A rows), 32 tiles
    const int m0 = (blk >> 5) * BN;    // m tile (B rows), 18 tiles

    const uint32_t sbase = smem_u32(dsmem);

    const __half* A_g = g_Xh + ((size_t)b * HW + n0) * CIN;
    const __half* B_g = g_Wh + (size_t)m0 * K_GEMM;

    auto copy_chunk = [&](int ch) {
        const uint32_t sb = sbase + (ch & 1) * STAGE_B;
        const int k0 = ch * BK;
#pragma unroll
        for (int t = 0; t < 4; t++) {
            int u = t * 256 + tid;          // 0..1023
            int r = u >> 3;                 // row 0..127
            int q = u & 7;                  // 16B unit in row
            uint32_t doff = swz((uint32_t)(r * 128 + q * 16));
            CP16(sb + doff,          A_g + (size_t)r * CIN    + k0 + q * 8);
            CP16(sb + TILE_B + doff, B_g + (size_t)r * K_GEMM + k0 + q * 8);
        }
        CP_COMMIT();
    };

    float acc[4][4][4] = {};   // [mf][jj][reg]

    const int arow = warp_m * 64 + (lane & 15);
    const int acol = (lane & 16);
    const int nloc = ((lane >> 4) & 1) * 8 + (lane & 7);
    const int bcol = ((lane >> 3) & 1) * 16;

    copy_chunk(0);
    copy_chunk(1);

    for (int ch = 0; ch < NCHUNK; ch++) {
        if (ch < NCHUNK - 1) { CP_WAIT(1); } else { CP_WAIT(0); }
        __syncthreads();

        const uint32_t sb = sbase + (ch & 1) * STAGE_B;
        const uint32_t tA = sb;
        const uint32_t tB = sb + TILE_B;

#pragma unroll
        for (int kf = 0; kf < BK / 16; kf++) {
            uint32_t af[4][4];
#pragma unroll
            for (int mf = 0; mf < 4; mf++) {
                uint32_t off = swz((uint32_t)((arow + mf * 16) * 128 + kf * 32 + acol));
                ldsm_x4(af[mf], tA + off);
            }
            uint32_t bf[4][2];
#pragma unroll
            for (int jp = 0; jp < 2; jp++) {
                uint32_t off = swz((uint32_t)((warp_n * 32 + jp * 16 + nloc) * 128 + kf * 32 + bcol));
                uint32_t rh[4];
                ldsm_x4(rh, tB + off);
                bf[2*jp][0]   = rh[0]; bf[2*jp][1]   = rh[1];
                bf[2*jp+1][0] = rh[2]; bf[2*jp+1][1] = rh[3];
            }
#pragma unroll
            for (int mf = 0; mf < 4; mf++)
#pragma unroll
                for (int jj = 0; jj < 4; jj++)
                    mma_fp16(acc[mf][jj], af[mf], bf[jj]);
        }

        if (ch + 2 < NCHUNK) {
            __syncthreads();
            copy_chunk(ch + 2);
        }
    }
    __syncthreads();   // smem quiesced before caller reuses it

    // ---- epilogue: rows = n, cols = o (m within fixed tap k), fp16 stores ----
    const int k_blk = m0 >> 8;          // tap index
    const int o0    = m0 & 255;         // o base (0 or 128)
    __half* Gout = g_Gh + ((size_t)(b * K2 + k_blk)) * HW * COUT;

    const int rbase = n0 + warp_m * 64 + (lane >> 2);          // n
    const int cbase = o0 + warp_n * 32 + (lane & 3) * 2;       // o
#pragma unroll
    for (int mf = 0; mf < 4; mf++) {
#pragma unroll
        for (int jj = 0; jj < 4; jj++) {
            int n = rbase + mf * 16;
            int o = cbase + jj * 8;
            *reinterpret_cast<__half2*>(&Gout[(size_t)n * COUT + o]) =
                __floats2half2_rn(acc[mf][jj][0], acc[mf][jj][1]);
            *reinterpret_cast<__half2*>(&Gout[(size_t)(n + 8) * COUT + o]) =
                __floats2half2_rn(acc[mf][jj][2], acc[mf][jj][3]);
        }
    }
}

// ---------------------------------------------------------------------------
// Combine body: coalesced bilinear gather over fp16 G[b][k][n][o]
//   1 warp per pixel, 8 pixels per block; lane owns 8 o-channels.
// ---------------------------------------------------------------------------
__device__ void combine_body(const float* __restrict__ offset,
                             const float* __restrict__ mask,
                             const float* __restrict__ bias,
                             float* __restrict__ out, int b, int blk) {
    __shared__ int4   s_idx[PPB][K2];
    __shared__ float4 s_cw[PPB][K2];
    __shared__ float  s_out[PPB][COUT];

    const int p0   = blk * PPB;
    const int tid  = threadIdx.x;
    const int w    = tid >> 5;
    const int lane = tid & 31;
    const int p    = p0 + w;

    if (lane < K2) {
        const int k  = lane;
        const int py = p >> 6;
        const int px = p & 63;

        float dy = offset[((b * 2 * K2) + 2 * k    ) * HW + p];
        float dx = offset[((b * 2 * K2) + 2 * k + 1) * HW + p];
        float m  = mask[(b * K2 + k) * HW + p];

        float yy = (float)(py - 1 + (k / 3)) + dy;
        float xx = (float)(px - 1 + (k % 3)) + dx;

        float y0f = floorf(yy), x0f = floorf(xx);
        float ly = yy - y0f, lx = xx - x0f;
        float hy = 1.0f - ly, hx = 1.0f - lx;
        int y0 = (int)y0f, x0 = (int)x0f;
        int y1 = y0 + 1,   x1 = x0 + 1;

        bool vy0 = (y0 >= 0) && (y0 < HDIM);
        bool vy1 = (y1 >= 0) && (y1 < HDIM);
        bool vx0 = (x0 >= 0) && (x0 < WDIM);
        bool vx1 = (x1 >= 0) && (x1 < WDIM);

        int cy0 = min(max(y0, 0), HDIM - 1);
        int cy1 = min(max(y1, 0), HDIM - 1);
        int cx0 = min(max(x0, 0), WDIM - 1);
        int cx1 = min(max(x1, 0), WDIM - 1);

        s_idx[w][k] = make_int4(cy0 * WDIM + cx0, cy0 * WDIM + cx1,
                                cy1 * WDIM + cx0, cy1 * WDIM + cx1);
        s_cw[w][k]  = make_float4((vy0 && vx0) ? hy * hx * m : 0.0f,
                                  (vy0 && vx1) ? hy * lx * m : 0.0f,
                                  (vy1 && vx0) ? ly * hx * m : 0.0f,
                                  (vy1 && vx1) ? ly * lx * m : 0.0f);
    }
    __syncwarp();

    const int o8 = lane * 8;
    float acc[8];
    {
        const float4* b4 = reinterpret_cast<const float4*>(bias + o8);
        float4 b0 = b4[0], b1 = b4[1];
        acc[0] = b0.x; acc[1] = b0.y; acc[2] = b0.z; acc[3] = b0.w;
        acc[4] = b1.x; acc[5] = b1.y; acc[6] = b1.z; acc[7] = b1.w;
    }

#pragma unroll
    for (int k = 0; k < K2; k++) {
        int4   id = s_idx[w][k];
        float4 cw = s_cw[w][k];
        const __half* base = g_Gh + ((size_t)(b * K2 + k)) * HW * COUT + o8;

        uint4 v0 = *reinterpret_cast<const uint4*>(base + (size_t)id.x * COUT);
        uint4 v1 = *reinterpret_cast<const uint4*>(base + (size_t)id.y * COUT);
        uint4 v2 = *reinterpret_cast<const uint4*>(base + (size_t)id.z * COUT);
        uint4 v3 = *reinterpret_cast<const uint4*>(base + (size_t)id.w * COUT);

        const __half2* h0 = reinterpret_cast<const __half2*>(&v0);
        const __half2* h1 = reinterpret_cast<const __half2*>(&v1);
        const __half2* h2 = reinterpret_cast<const __half2*>(&v2);
        const __half2* h3 = reinterpret_cast<const __half2*>(&v3);

#pragma unroll
        for (int j = 0; j < 4; j++) {
            float2 a = __half22float2(h0[j]);
            float2 bb = __half22float2(h1[j]);
            float2 c = __half22float2(h2[j]);
            float2 d = __half22float2(h3[j]);
            acc[2*j]   += cw.x * a.x + cw.y * bb.x + cw.z * c.x + cw.w * d.x;
            acc[2*j+1] += cw.x * a.y + cw.y * bb.y + cw.z * c.y + cw.w * d.y;
        }
    }

#pragma unroll
    for (int j = 0; j < 8; j++) s_out[w][o8 + j] = acc[j];
    __syncthreads();

    {
        const int o = tid;
        float4 r0 = make_float4(s_out[0][o], s_out[1][o], s_out[2][o], s_out[3][o]);
        float4 r1 = make_float4(s_out[4][o], s_out[5][o], s_out[6][o], s_out[7][o]);
        float* dst = out + ((size_t)(b * COUT + o)) * HW + p0;
        *reinterpret_cast<float4*>(dst)     = r0;
        *reinterpret_cast<float4*>(dst + 4) = r1;
    }
    __syncthreads();   // smem quiesced before next item reuses it
}

// ---------------------------------------------------------------------------
// Persistent pipeline: ph0 GEMM(b0) | ph1..3 GEMM(b) ∥ combine(b-1) | ph4 combine(b3)
// ---------------------------------------------------------------------------
__global__ __launch_bounds__(256, 2) void pipeline_kernel(
    const float* __restrict__ offset, const float* __restrict__ mask,
    const float* __restrict__ bias, float* __restrict__ out) {
    const unsigned gen0 = *(volatile unsigned*)&g_gen;  // stable until first barrier

    for (int ph = 0; ph < BATCH + 1; ph++) {
        const int ng = (ph < BATCH) ? GEMM_BLOCKS : 0;
        const int nc = (ph >= 1)    ? COMB_BLOCKS : 0;
        for (int w = blockIdx.x; w < ng + nc; w += NCTAS) {
            if (w < ng) gemm_body(ph, w);
            else        combine_body(offset, mask, bias, out, ph - 1, w - ng);
        }
        if (ph < BATCH) grid_barrier(gen0 + (unsigned)ph + 1u);
    }
}

// ---------------------------------------------------------------------------
extern "C" void kernel_launch(void* const* d_in, const int* in_sizes, int n_in,
                              void* d_out, int out_size) {
    const float* x      = (const float*)d_in[0];   // [4,256,64,64]
    const float* offset = (const float*)d_in[1];   // [4,18,64,64]
    const float* mask   = (const float*)d_in[2];   // [4,9,64,64]
    const float* weight = (const float*)d_in[3];   // [256,256,3,3]
    const float* bias   = (const float*)d_in[4];   // [256]
    float* out = (float*)d_out;                    // [4,256,64,64]

    static bool attr_set = false;
    if (!attr_set) {
        cudaFuncSetAttribute(pipeline_kernel,
                             cudaFuncAttributeMaxDynamicSharedMemorySize, SMEM_DYN);
        attr_set = true;
    }

    pre_kernel<<<256 + BATCH * 1024, 256>>>(weight, x);
    pipeline_kernel<<<NCTAS, 256, SMEM_DYN>>>(offset, mask, bias, out);
}

// round 12
// speedup vs baseline: 1.1134x; 1.1134x over previous
#include <cuda_runtime.h>
#include <cuda_fp16.h>
#include <cstdint>

// ---------------- problem constants ----------------
#define CIN    256
#define COUT   256
#define HDIM   64
#define WDIM   64
#define BATCH  4
#define K2     9
#define HW     4096
#define M_GEMM 2304          // K2 * COUT
#define K_GEMM 256           // CIN

// ---------------- GEMM tiling ----------------
#define BM 128                         // n-tile rows
#define BN 128                         // m-tile cols
#define BK 64                          // fp16 elements per chunk (128B rows)
#define NCHUNK (K_GEMM / BK)           // 4
#define TILE_B (BM * BK * 2)           // 16384 bytes per operand tile
#define STAGE_B (2 * TILE_B)           // A, B = 32 KB
#define SMEM_DYN (2 * STAGE_B)         // 64 KB

#define CPB 4                          // pixels per combine CTA (2 warps/pixel)

// ---------------- scratch (device globals) ----------------
__device__ __half g_Wh[M_GEMM * K_GEMM];      // [m][c]
__device__ __half g_Xh[BATCH * HW * CIN];     // [b][n][c]
// layout: G[b][k][n][o]  (o contiguous), fp16.  75.5 MB
__device__ __half g_Gh[(size_t)BATCH * K2 * HW * COUT];

// ---------------- PTX helpers ----------------
__device__ __forceinline__ uint32_t smem_u32(const void* p) {
    uint32_t a;
    asm("{ .reg .u64 t; cvta.to.shared.u64 t, %1; cvt.u32.u64 %0, t; }" : "=r"(a) : "l"(p));
    return a;
}
#define CP16(dst, src)  asm volatile("cp.async.cg.shared.global [%0], [%1], 16;" :: "r"(dst), "l"(src) : "memory")
#define CP_COMMIT()     asm volatile("cp.async.commit_group;" ::: "memory")
#define CP_WAIT(n)      asm volatile("cp.async.wait_group %0;" :: "n"(n) : "memory")

__device__ __forceinline__ void ldsm_x4(uint32_t* r, uint32_t addr) {
    asm volatile("ldmatrix.sync.aligned.m8n8.x4.shared.b16 {%0,%1,%2,%3}, [%4];"
                 : "=r"(r[0]), "=r"(r[1]), "=r"(r[2]), "=r"(r[3]) : "r"(addr));
}
__device__ __forceinline__ void mma_fp16(float* d, const uint32_t* a, const uint32_t* b) {
    asm volatile("mma.sync.aligned.m16n8k16.row.col.f32.f16.f16.f32 "
                 "{%0,%1,%2,%3}, {%4,%5,%6,%7}, {%8,%9}, {%0,%1,%2,%3};"
                 : "+f"(d[0]), "+f"(d[1]), "+f"(d[2]), "+f"(d[3])
                 : "r"(a[0]), "r"(a[1]), "r"(a[2]), "r"(a[3]), "r"(b[0]), "r"(b[1]));
}
__device__ __forceinline__ uint32_t swz(uint32_t off) { return off ^ ((off >> 3) & 0x70); }

// ---------------------------------------------------------------------------
// Kernel 1: blend (blocks 0..255) ∥ transpose all batches (blocks 256..4351)
// ---------------------------------------------------------------------------
__global__ __launch_bounds__(256) void pre_kernel(const float* __restrict__ weight,
                                                  const float* __restrict__ X) {
    const int tid = threadIdx.x;
    if (blockIdx.x < 256) {
        // ---- circle-blend weights -> fp16, K-major [m][c] ----
        int t = blockIdx.x * 256 + tid;
        int o = t >> 8;
        int c = t & 255;
        const float* wp = weight + ((size_t)(o * CIN + c)) * K2;
        float w0 = wp[0], w1 = wp[1], w2 = wp[2];
        float w3 = wp[3], w4 = wp[4], w5 = wp[5];
        float w6 = wp[6], w7 = wp[7], w8 = wp[8];

        const float A  = 0.7071067811865476f;
        const float Bc = 1.0f - 0.7071067811865476f;

        float t01 = A * w0 + Bc * w1;
        float t34 = A * w3 + Bc * w4;
        float t12 = Bc * w1 + A * w2;
        float t45 = Bc * w4 + A * w5;
        float t67 = A * w6 + Bc * w7;
        float t78 = Bc * w7 + A * w8;

        float nw[K2];
        nw[0] = A * t01 + Bc * t34;  nw[1] = w1;
        nw[2] = A * t12 + Bc * t45;  nw[3] = w3;  nw[4] = w4;  nw[5] = w5;
        nw[6] = Bc * t34 + A * t67;  nw[7] = w7;
        nw[8] = Bc * t45 + A * t78;

#pragma unroll
        for (int k = 0; k < K2; k++)
            g_Wh[(size_t)(k * COUT + o) * K_GEMM + c] = __float2half_rn(nw[k]);
    } else {
        // ---- transpose x[b][c][n] -> Xt[b][n][c] in fp16 ----
        __shared__ float tle[32][33];
        int u  = blockIdx.x - 256;       // 0..4095
        int b  = u >> 10;                // 4 batches
        int r  = u & 1023;               // 1024 tiles per batch
        int n0 = (r & 127) * 32;
        int c0 = (r >> 7) * 32;
        int tx = tid & 31, ty = tid >> 5;

        const float* src = X + ((size_t)b * CIN + c0) * HW + n0;
#pragma unroll
        for (int i = ty; i < 32; i += 8)
            tle[i][tx] = src[(size_t)i * HW + tx];
        __syncthreads();

        __half* dh = g_Xh + ((size_t)b * HW + n0) * CIN + c0;
#pragma unroll
        for (int i = ty; i < 32; i += 8)
            dh[(size_t)i * CIN + tx] = __float2half_rn(tle[tx][i]);
    }
}

// ---------------------------------------------------------------------------
// Kernel 2: fp16 single-pass GEMM (A = Xt rows n, B = W rows m), all batches
//   G[b][k][n][o] = sum_c Xh[b][n][c] * Wh[k*256+o][c]   (stored fp16)
// ---------------------------------------------------------------------------
extern __shared__ __align__(1024) unsigned char dsmem[];

__global__ __launch_bounds__(256, 2) void gemm_fp16_kernel() {
    const int tid  = threadIdx.x;
    const int wid  = tid >> 5;
    const int lane = tid & 31;
    const int warp_m = wid >> 2;       // 0..1  (64 n-rows each)
    const int warp_n = wid & 3;        // 0..3  (32 m-cols each)

    const int b  = blockIdx.z;
    const int n0 = blockIdx.x * BM;    // n tile (A rows)
    const int m0 = blockIdx.y * BN;    // m tile (B rows)

    const uint32_t sbase = smem_u32(dsmem);

    const __half* A_g = g_Xh + ((size_t)b * HW + n0) * CIN;
    const __half* B_g = g_Wh + (size_t)m0 * K_GEMM;

    auto copy_chunk = [&](int ch) {
        const uint32_t sb = sbase + (ch & 1) * STAGE_B;
        const int k0 = ch * BK;
#pragma unroll
        for (int t = 0; t < 4; t++) {
            int u = t * 256 + tid;          // 0..1023
            int r = u >> 3;                 // row 0..127
            int q = u & 7;                  // 16B unit in row
            uint32_t doff = swz((uint32_t)(r * 128 + q * 16));
            CP16(sb + doff,          A_g + (size_t)r * CIN    + k0 + q * 8);
            CP16(sb + TILE_B + doff, B_g + (size_t)r * K_GEMM + k0 + q * 8);
        }
        CP_COMMIT();
    };

    float acc[4][4][4] = {};   // [mf][jj][reg]

    const int arow = warp_m * 64 + (lane & 15);
    const int acol = (lane & 16);
    const int nloc = ((lane >> 4) & 1) * 8 + (lane & 7);
    const int bcol = ((lane >> 3) & 1) * 16;

    copy_chunk(0);
    copy_chunk(1);

    for (int ch = 0; ch < NCHUNK; ch++) {
        if (ch < NCHUNK - 1) { CP_WAIT(1); } else { CP_WAIT(0); }
        __syncthreads();

        const uint32_t sb = sbase + (ch & 1) * STAGE_B;
        const uint32_t tA = sb;
        const uint32_t tB = sb + TILE_B;

#pragma unroll
        for (int kf = 0; kf < BK / 16; kf++) {
            uint32_t af[4][4];
#pragma unroll
            for (int mf = 0; mf < 4; mf++) {
                uint32_t off = swz((uint32_t)((arow + mf * 16) * 128 + kf * 32 + acol));
                ldsm_x4(af[mf], tA + off);
            }
            uint32_t bf[4][2];
#pragma unroll
            for (int jp = 0; jp < 2; jp++) {
                uint32_t off = swz((uint32_t)((warp_n * 32 + jp * 16 + nloc) * 128 + kf * 32 + bcol));
                uint32_t rh[4];
                ldsm_x4(rh, tB + off);
                bf[2*jp][0]   = rh[0]; bf[2*jp][1]   = rh[1];
                bf[2*jp+1][0] = rh[2]; bf[2*jp+1][1] = rh[3];
            }
#pragma unroll
            for (int mf = 0; mf < 4; mf++)
#pragma unroll
                for (int jj = 0; jj < 4; jj++)
                    mma_fp16(acc[mf][jj], af[mf], bf[jj]);
        }

        if (ch + 2 < NCHUNK) {
            __syncthreads();
            copy_chunk(ch + 2);
        }
    }

    // ---- epilogue: rows = n, cols = o (m within fixed tap k), fp16 stores ----
    const int k_blk = m0 >> 8;          // tap index
    const int o0    = m0 & 255;         // o base (0 or 128)
    __half* Gout = g_Gh + ((size_t)(b * K2 + k_blk)) * HW * COUT;

    const int rbase = n0 + warp_m * 64 + (lane >> 2);          // n
    const int cbase = o0 + warp_n * 32 + (lane & 3) * 2;       // o
#pragma unroll
    for (int mf = 0; mf < 4; mf++) {
#pragma unroll
        for (int jj = 0; jj < 4; jj++) {
            int n = rbase + mf * 16;
            int o = cbase + jj * 8;
            *reinterpret_cast<__half2*>(&Gout[(size_t)n * COUT + o]) =
                __floats2half2_rn(acc[mf][jj][0], acc[mf][jj][1]);
            *reinterpret_cast<__half2*>(&Gout[(size_t)(n + 8) * COUT + o]) =
                __floats2half2_rn(acc[mf][jj][2], acc[mf][jj][3]);
        }
    }
}

// ---------------------------------------------------------------------------
// Kernel 3: combine — 2 warps per pixel, 4 o-channels per lane (uint2 gathers)
//   Low register pressure -> 5-6 CTAs/SM -> latency hidden toward LTS floor.
// ---------------------------------------------------------------------------
__global__ __launch_bounds__(256) void combine_kernel(
    const float* __restrict__ offset,
    const float* __restrict__ mask,
    const float* __restrict__ bias,
    float* __restrict__ out)
{
    __shared__ int4   s_idx[CPB][K2];
    __shared__ float4 s_cw[CPB][K2];
    __shared__ float  s_out[CPB][COUT];

    const int b    = blockIdx.y;
    const int p0   = blockIdx.x * CPB;
    const int tid  = threadIdx.x;
    const int w    = tid >> 5;
    const int lane = tid & 31;
    const int pxl  = w >> 1;          // 0..3 pixel within CTA
    const int half = w & 1;           // which 128-channel half
    const int p    = p0 + pxl;

    if (half == 0 && lane < K2) {
        const int k  = lane;
        const int py = p >> 6;
        const int px = p & 63;

        float dy = offset[((b * 2 * K2) + 2 * k    ) * HW + p];
        float dx = offset[((b * 2 * K2) + 2 * k + 1) * HW + p];
        float m  = mask[(b * K2 + k) * HW + p];

        float yy = (float)(py - 1 + (k / 3)) + dy;
        float xx = (float)(px - 1 + (k % 3)) + dx;

        float y0f = floorf(yy), x0f = floorf(xx);
        float ly = yy - y0f, lx = xx - x0f;
        float hy = 1.0f - ly, hx = 1.0f - lx;
        int y0 = (int)y0f, x0 = (int)x0f;
        int y1 = y0 + 1,   x1 = x0 + 1;

        bool vy0 = (y0 >= 0) && (y0 < HDIM);
        bool vy1 = (y1 >= 0) && (y1 < HDIM);
        bool vx0 = (x0 >= 0) && (x0 < WDIM);
        bool vx1 = (x1 >= 0) && (x1 < WDIM);

        int cy0 = min(max(y0, 0), HDIM - 1);
        int cy1 = min(max(y1, 0), HDIM - 1);
        int cx0 = min(max(x0, 0), WDIM - 1);
        int cx1 = min(max(x1, 0), WDIM - 1);

        s_idx[pxl][k] = make_int4(cy0 * WDIM + cx0, cy0 * WDIM + cx1,
                                  cy1 * WDIM + cx0, cy1 * WDIM + cx1);
        s_cw[pxl][k]  = make_float4((vy0 && vx0) ? hy * hx * m : 0.0f,
                                    (vy0 && vx1) ? hy * lx * m : 0.0f,
                                    (vy1 && vx0) ? ly * hx * m : 0.0f,
                                    (vy1 && vx1) ? ly * lx * m : 0.0f);
    }
    __syncthreads();

    const int o4 = (half * 32 + lane) * 4;   // 0..252, 4 channels per lane
    float acc[4];
    {
        float4 b0 = *reinterpret_cast<const float4*>(bias + o4);
        acc[0] = b0.x; acc[1] = b0.y; acc[2] = b0.z; acc[3] = b0.w;
    }

#pragma unroll
    for (int k = 0; k < K2; k++) {
        int4   id = s_idx[pxl][k];
        float4 cw = s_cw[pxl][k];
        const __half* base = g_Gh + ((size_t)(b * K2 + k)) * HW * COUT + o4;

        uint2 v0 = *reinterpret_cast<const uint2*>(base + (size_t)id.x * COUT);
        uint2 v1 = *reinterpret_cast<const uint2*>(base + (size_t)id.y * COUT);
        uint2 v2 = *reinterpret_cast<const uint2*>(base + (size_t)id.z * COUT);
        uint2 v3 = *reinterpret_cast<const uint2*>(base + (size_t)id.w * COUT);

        const __half2* h0 = reinterpret_cast<const __half2*>(&v0);
        const __half2* h1 = reinterpret_cast<const __half2*>(&v1);
        const __half2* h2 = reinterpret_cast<const __half2*>(&v2);
        const __half2* h3 = reinterpret_cast<const __half2*>(&v3);

#pragma unroll
        for (int j = 0; j < 2; j++) {
            float2 a  = __half22float2(h0[j]);
            float2 bb = __half22float2(h1[j]);
            float2 c  = __half22float2(h2[j]);
            float2 d  = __half22float2(h3[j]);
            acc[2*j]   += cw.x * a.x + cw.y * bb.x + cw.z * c.x + cw.w * d.x;
            acc[2*j+1] += cw.x * a.y + cw.y * bb.y + cw.z * c.y + cw.w * d.y;
        }
    }

    *reinterpret_cast<float4*>(&s_out[pxl][o4]) =
        make_float4(acc[0], acc[1], acc[2], acc[3]);
    __syncthreads();

    {
        const int o = tid;
        float4 r0 = make_float4(s_out[0][o], s_out[1][o], s_out[2][o], s_out[3][o]);
        *reinterpret_cast<float4*>(out + ((size_t)(b * COUT + o)) * HW + p0) = r0;
    }
}

// ---------------------------------------------------------------------------
extern "C" void kernel_launch(void* const* d_in, const int* in_sizes, int n_in,
                              void* d_out, int out_size) {
    const float* x      = (const float*)d_in[0];   // [4,256,64,64]
    const float* offset = (const float*)d_in[1];   // [4,18,64,64]
    const float* mask   = (const float*)d_in[2];   // [4,9,64,64]
    const float* weight = (const float*)d_in[3];   // [256,256,3,3]
    const float* bias   = (const float*)d_in[4];   // [256]
    float* out = (float*)d_out;                    // [4,256,64,64]

    static bool attr_set = false;
    if (!attr_set) {
        cudaFuncSetAttribute(gemm_fp16_kernel,
                             cudaFuncAttributeMaxDynamicSharedMemorySize, SMEM_DYN);
        attr_set = true;
    }

    pre_kernel<<<256 + BATCH * 1024, 256>>>(weight, x);
    gemm_fp16_kernel<<<dim3(HW / BM, M_GEMM / BN, BATCH), 256, SMEM_DYN>>>();
    combine_kernel<<<dim3(HW / CPB, BATCH), 256>>>(offset, mask, bias, out);
}

// round 13
// speedup vs baseline: 1.2053x; 1.0825x over previous
#include <cuda_runtime.h>
#include <cuda_fp16.h>
#include <cstdint>

// ---------------- problem constants ----------------
#define CIN    256
#define COUT   256
#define HDIM   64
#define WDIM   64
#define BATCH  4
#define K2     9
#define HW     4096
#define M_GEMM 2304          // K2 * COUT
#define K_GEMM 256           // CIN

// ---------------- GEMM tiling ----------------
#define BM 128                         // n-tile rows
#define BN 128                         // m-tile cols
#define BK 64                          // fp16 elements per chunk (128B rows)
#define NCHUNK (K_GEMM / BK)           // 4
#define TILE_B (BM * BK * 2)           // 16384 bytes per operand tile
#define STAGE_B (2 * TILE_B)           // A, B = 32 KB
#define SMEM_DYN (2 * STAGE_B)         // 64 KB

#define PPB 8                          // pixels per combine CTA (1 warp/pixel)

// ---------------- scratch (device globals) ----------------
__device__ __half g_Wh[M_GEMM * K_GEMM];      // [m][c]
__device__ __half g_Xh[BATCH * HW * CIN];     // [b][n][c]
// layout: G[b][k][n][o]  (o contiguous), fp16.  75.5 MB
__device__ __half g_Gh[(size_t)BATCH * K2 * HW * COUT];

// ---------------- PTX helpers ----------------
__device__ __forceinline__ uint32_t smem_u32(const void* p) {
    uint32_t a;
    asm("{ .reg .u64 t; cvta.to.shared.u64 t, %1; cvt.u32.u64 %0, t; }" : "=r"(a) : "l"(p));
    return a;
}
#define CP16(dst, src)  asm volatile("cp.async.cg.shared.global [%0], [%1], 16;" :: "r"(dst), "l"(src) : "memory")
#define CP_COMMIT()     asm volatile("cp.async.commit_group;" ::: "memory")
#define CP_WAIT(n)      asm volatile("cp.async.wait_group %0;" :: "n"(n) : "memory")

__device__ __forceinline__ void ldsm_x4(uint32_t* r, uint32_t addr) {
    asm volatile("ldmatrix.sync.aligned.m8n8.x4.shared.b16 {%0,%1,%2,%3}, [%4];"
                 : "=r"(r[0]), "=r"(r[1]), "=r"(r[2]), "=r"(r[3]) : "r"(addr));
}
__device__ __forceinline__ void mma_fp16(float* d, const uint32_t* a, const uint32_t* b) {
    asm volatile("mma.sync.aligned.m16n8k16.row.col.f32.f16.f16.f32 "
                 "{%0,%1,%2,%3}, {%4,%5,%6,%7}, {%8,%9}, {%0,%1,%2,%3};"
                 : "+f"(d[0]), "+f"(d[1]), "+f"(d[2]), "+f"(d[3])
                 : "r"(a[0]), "r"(a[1]), "r"(a[2]), "r"(a[3]), "r"(b[0]), "r"(b[1]));
}
__device__ __forceinline__ uint32_t swz(uint32_t off) { return off ^ ((off >> 3) & 0x70); }

// ---------------------------------------------------------------------------
// Kernel 1: blend (blocks 0..255) ∥ transpose all batches (blocks 256..4351)
// ---------------------------------------------------------------------------
__global__ __launch_bounds__(256) void pre_kernel(const float* __restrict__ weight,
                                                  const float* __restrict__ X) {
    const int tid = threadIdx.x;
    if (blockIdx.x < 256) {
        // ---- circle-blend weights -> fp16, K-major [m][c] ----
        int t = blockIdx.x * 256 + tid;
        int o = t >> 8;
        int c = t & 255;
        const float* wp = weight + ((size_t)(o * CIN + c)) * K2;
        float w0 = wp[0], w1 = wp[1], w2 = wp[2];
        float w3 = wp[3], w4 = wp[4], w5 = wp[5];
        float w6 = wp[6], w7 = wp[7], w8 = wp[8];

        const float A  = 0.7071067811865476f;
        const float Bc = 1.0f - 0.7071067811865476f;

        float t01 = A * w0 + Bc * w1;
        float t34 = A * w3 + Bc * w4;
        float t12 = Bc * w1 + A * w2;
        float t45 = Bc * w4 + A * w5;
        float t67 = A * w6 + Bc * w7;
        float t78 = Bc * w7 + A * w8;

        float nw[K2];
        nw[0] = A * t01 + Bc * t34;  nw[1] = w1;
        nw[2] = A * t12 + Bc * t45;  nw[3] = w3;  nw[4] = w4;  nw[5] = w5;
        nw[6] = Bc * t34 + A * t67;  nw[7] = w7;
        nw[8] = Bc * t45 + A * t78;

#pragma unroll
        for (int k = 0; k < K2; k++)
            g_Wh[(size_t)(k * COUT + o) * K_GEMM + c] = __float2half_rn(nw[k]);
    } else {
        // ---- transpose x[b][c][n] -> Xt[b][n][c] in fp16 ----
        __shared__ float tle[32][33];
        int u  = blockIdx.x - 256;       // 0..4095
        int b  = u >> 10;                // 4 batches
        int r  = u & 1023;               // 1024 tiles per batch
        int n0 = (r & 127) * 32;
        int c0 = (r >> 7) * 32;
        int tx = tid & 31, ty = tid >> 5;

        const float* src = X + ((size_t)b * CIN + c0) * HW + n0;
#pragma unroll
        for (int i = ty; i < 32; i += 8)
            tle[i][tx] = src[(size_t)i * HW + tx];
        __syncthreads();

        __half* dh = g_Xh + ((size_t)b * HW + n0) * CIN + c0;
#pragma unroll
        for (int i = ty; i < 32; i += 8)
            dh[(size_t)i * CIN + tx] = __float2half_rn(tle[tx][i]);
    }
}

// ---------------------------------------------------------------------------
// Kernel 2: fp16 single-pass GEMM (A = Xt rows n, B = W rows m), all batches
//   G[b][k][n][o] = sum_c Xh[b][n][c] * Wh[k*256+o][c]   (stored fp16)
// ---------------------------------------------------------------------------
extern __shared__ __align__(1024) unsigned char dsmem[];

__global__ __launch_bounds__(256, 2) void gemm_fp16_kernel() {
    const int tid  = threadIdx.x;
    const int wid  = tid >> 5;
    const int lane = tid & 31;
    const int warp_m = wid >> 2;       // 0..1  (64 n-rows each)
    const int warp_n = wid & 3;        // 0..3  (32 m-cols each)

    const int b  = blockIdx.z;
    const int n0 = blockIdx.x * BM;    // n tile (A rows)
    const int m0 = blockIdx.y * BN;    // m tile (B rows)

    const uint32_t sbase = smem_u32(dsmem);

    const __half* A_g = g_Xh + ((size_t)b * HW + n0) * CIN;
    const __half* B_g = g_Wh + (size_t)m0 * K_GEMM;

    auto copy_chunk = [&](int ch) {
        const uint32_t sb = sbase + (ch & 1) * STAGE_B;
        const int k0 = ch * BK;
#pragma unroll
        for (int t = 0; t < 4; t++) {
            int u = t * 256 + tid;          // 0..1023
            int r = u >> 3;                 // row 0..127
            int q = u & 7;                  // 16B unit in row
            uint32_t doff = swz((uint32_t)(r * 128 + q * 16));
            CP16(sb + doff,          A_g + (size_t)r * CIN    + k0 + q * 8);
            CP16(sb + TILE_B + doff, B_g + (size_t)r * K_GEMM + k0 + q * 8);
        }
        CP_COMMIT();
    };

    float acc[4][4][4] = {};   // [mf][jj][reg]

    const int arow = warp_m * 64 + (lane & 15);
    const int acol = (lane & 16);
    const int nloc = ((lane >> 4) & 1) * 8 + (lane & 7);
    const int bcol = ((lane >> 3) & 1) * 16;

    copy_chunk(0);
    copy_chunk(1);

    for (int ch = 0; ch < NCHUNK; ch++) {
        if (ch < NCHUNK - 1) { CP_WAIT(1); } else { CP_WAIT(0); }
        __syncthreads();

        const uint32_t sb = sbase + (ch & 1) * STAGE_B;
        const uint32_t tA = sb;
        const uint32_t tB = sb + TILE_B;

#pragma unroll
        for (int kf = 0; kf < BK / 16; kf++) {
            uint32_t af[4][4];
#pragma unroll
            for (int mf = 0; mf < 4; mf++) {
                uint32_t off = swz((uint32_t)((arow + mf * 16) * 128 + kf * 32 + acol));
                ldsm_x4(af[mf], tA + off);
            }
            uint32_t bf[4][2];
#pragma unroll
            for (int jp = 0; jp < 2; jp++) {
                uint32_t off = swz((uint32_t)((warp_n * 32 + jp * 16 + nloc) * 128 + kf * 32 + bcol));
                uint32_t rh[4];
                ldsm_x4(rh, tB + off);
                bf[2*jp][0]   = rh[0]; bf[2*jp][1]   = rh[1];
                bf[2*jp+1][0] = rh[2]; bf[2*jp+1][1] = rh[3];
            }
#pragma unroll
            for (int mf = 0; mf < 4; mf++)
#pragma unroll
                for (int jj = 0; jj < 4; jj++)
                    mma_fp16(acc[mf][jj], af[mf], bf[jj]);
        }

        if (ch + 2 < NCHUNK) {
            __syncthreads();
            copy_chunk(ch + 2);
        }
    }

    // ---- epilogue: rows = n, cols = o (m within fixed tap k), fp16 stores ----
    const int k_blk = m0 >> 8;          // tap index
    const int o0    = m0 & 255;         // o base (0 or 128)
    __half* Gout = g_Gh + ((size_t)(b * K2 + k_blk)) * HW * COUT;

    const int rbase = n0 + warp_m * 64 + (lane >> 2);          // n
    const int cbase = o0 + warp_n * 32 + (lane & 3) * 2;       // o
#pragma unroll
    for (int mf = 0; mf < 4; mf++) {
#pragma unroll
        for (int jj = 0; jj < 4; jj++) {
            int n = rbase + mf * 16;
            int o = cbase + jj * 8;
            *reinterpret_cast<__half2*>(&Gout[(size_t)n * COUT + o]) =
                __floats2half2_rn(acc[mf][jj][0], acc[mf][jj][1]);
            *reinterpret_cast<__half2*>(&Gout[(size_t)(n + 8) * COUT + o]) =
                __floats2half2_rn(acc[mf][jj][2], acc[mf][jj][3]);
        }
    }
}

// ---------------------------------------------------------------------------
// Kernel 3: combine — coalesced bilinear gather over fp16 G[b][k][n][o]
//   1 warp per pixel, 8 pixels per CTA; lane owns 8 o-channels (16B gathers).
//   launch_bounds(256,5): cap regs at 51 -> 5 CTAs/SM for latency hiding.
// ---------------------------------------------------------------------------
__global__ __launch_bounds__(256, 5) void combine_kernel(
    const float* __restrict__ offset,
    const float* __restrict__ mask,
    const float* __restrict__ bias,
    float* __restrict__ out)
{
    __shared__ int4   s_idx[PPB][K2];
    __shared__ float4 s_cw[PPB][K2];
    __shared__ float  s_out[PPB][COUT];

    const int b    = blockIdx.y;
    const int p0   = blockIdx.x * PPB;
    const int tid  = threadIdx.x;
    const int w    = tid >> 5;
    const int lane = tid & 31;
    const int p    = p0 + w;

    if (lane < K2) {
        const int k  = lane;
        const int py = p >> 6;
        const int px = p & 63;

        float dy = offset[((b * 2 * K2) + 2 * k    ) * HW + p];
        float dx = offset[((b * 2 * K2) + 2 * k + 1) * HW + p];
        float m  = mask[(b * K2 + k) * HW + p];

        float yy = (float)(py - 1 + (k / 3)) + dy;
        float xx = (float)(px - 1 + (k % 3)) + dx;

        float y0f = floorf(yy), x0f = floorf(xx);
        float ly = yy - y0f, lx = xx - x0f;
        float hy = 1.0f - ly, hx = 1.0f - lx;
        int y0 = (int)y0f, x0 = (int)x0f;
        int y1 = y0 + 1,   x1 = x0 + 1;

        bool vy0 = (y0 >= 0) && (y0 < HDIM);
        bool vy1 = (y1 >= 0) && (y1 < HDIM);
        bool vx0 = (x0 >= 0) && (x0 < WDIM);
        bool vx1 = (x1 >= 0) && (x1 < WDIM);

        int cy0 = min(max(y0, 0), HDIM - 1);
        int cy1 = min(max(y1, 0), HDIM - 1);
        int cx0 = min(max(x0, 0), WDIM - 1);
        int cx1 = min(max(x1, 0), WDIM - 1);

        s_idx[w][k] = make_int4(cy0 * WDIM + cx0, cy0 * WDIM + cx1,
                                cy1 * WDIM + cx0, cy1 * WDIM + cx1);
        s_cw[w][k]  = make_float4((vy0 && vx0) ? hy * hx * m : 0.0f,
                                  (vy0 && vx1) ? hy * lx * m : 0.0f,
                                  (vy1 && vx0) ? ly * hx * m : 0.0f,
                                  (vy1 && vx1) ? ly * lx * m : 0.0f);
    }
    __syncwarp();

    const int o8 = lane * 8;
    float acc[8];
    {
        const float4* b4 = reinterpret_cast<const float4*>(bias + o8);
        float4 b0 = b4[0], b1 = b4[1];
        acc[0] = b0.x; acc[1] = b0.y; acc[2] = b0.z; acc[3] = b0.w;
        acc[4] = b1.x; acc[5] = b1.y; acc[6] = b1.z; acc[7] = b1.w;
    }

#pragma unroll
    for (int k = 0; k < K2; k++) {
        int4   id = s_idx[w][k];
        float4 cw = s_cw[w][k];
        const __half* base = g_Gh + ((size_t)(b * K2 + k)) * HW * COUT + o8;

        uint4 v0 = *reinterpret_cast<const uint4*>(base + (size_t)id.x * COUT);
        uint4 v1 = *reinterpret_cast<const uint4*>(base + (size_t)id.y * COUT);
        uint4 v2 = *reinterpret_cast<const uint4*>(base + (size_t)id.z * COUT);
        uint4 v3 = *reinterpret_cast<const uint4*>(base + (size_t)id.w * COUT);

        const __half2* h0 = reinterpret_cast<const __half2*>(&v0);
        const __half2* h1 = reinterpret_cast<const __half2*>(&v1);
        const __half2* h2 = reinterpret_cast<const __half2*>(&v2);
        const __half2* h3 = reinterpret_cast<const __half2*>(&v3);

#pragma unroll
        for (int j = 0; j < 4; j++) {
            float2 a = __half22float2(h0[j]);
            float2 bb = __half22float2(h1[j]);
            float2 c = __half22float2(h2[j]);
            float2 d = __half22float2(h3[j]);
            acc[2*j]   += cw.x * a.x + cw.y * bb.x + cw.z * c.x + cw.w * d.x;
            acc[2*j+1] += cw.x * a.y + cw.y * bb.y + cw.z * c.y + cw.w * d.y;
        }
    }

#pragma unroll
    for (int j = 0; j < 8; j++) s_out[w][o8 + j] = acc[j];
    __syncthreads();

    {
        const int o = tid;
        float4 r0 = make_float4(s_out[0][o], s_out[1][o], s_out[2][o], s_out[3][o]);
        float4 r1 = make_float4(s_out[4][o], s_out[5][o], s_out[6][o], s_out[7][o]);
        float* dst = out + ((size_t)(b * COUT + o)) * HW + p0;
        *reinterpret_cast<float4*>(dst)     = r0;
        *reinterpret_cast<float4*>(dst + 4) = r1;
    }
}

// ---------------------------------------------------------------------------
extern "C" void kernel_launch(void* const* d_in, const int* in_sizes, int n_in,
                              void* d_out, int out_size) {
    const float* x      = (const float*)d_in[0];   // [4,256,64,64]
    const float* offset = (const float*)d_in[1];   // [4,18,64,64]
    const float* mask   = (const float*)d_in[2];   // [4,9,64,64]
    const float* weight = (const float*)d_in[3];   // [256,256,3,3]
    const float* bias   = (const float*)d_in[4];   // [256]
    float* out = (float*)d_out;                    // [4,256,64,64]

    static bool attr_set = false;
    if (!attr_set) {
        cudaFuncSetAttribute(gemm_fp16_kernel,
                             cudaFuncAttributeMaxDynamicSharedMemorySize, SMEM_DYN);
        attr_set = true;
    }

    pre_kernel<<<256 + BATCH * 1024, 256>>>(weight, x);
    gemm_fp16_kernel<<<dim3(HW / BM, M_GEMM / BN, BATCH), 256, SMEM_DYN>>>();
    combine_kernel<<<dim3(HW / PPB, BATCH), 256>>>(offset, mask, bias, out);
}

// round 14
// speedup vs baseline: 1.2103x; 1.0041x over previous
#include <cuda_runtime.h>
#include <cuda_fp16.h>
#include <cstdint>

// ---------------- problem constants ----------------
#define CIN    256
#define COUT   256
#define HDIM   64
#define WDIM   64
#define BATCH  4
#define K2     9
#define HW     4096
#define M_GEMM 2304          // K2 * COUT
#define K_GEMM 256           // CIN

// ---------------- GEMM tiling ----------------
#define BM 128                         // n-tile rows
#define BN 128                         // m-tile cols
#define BK 64                          // fp16 elements per chunk (128B rows)
#define NCHUNK (K_GEMM / BK)           // 4
#define NSTAGE 3
#define TILE_B (BM * BK * 2)           // 16384 bytes per operand tile
#define STAGE_B (2 * TILE_B)           // A, B = 32 KB
#define SMEM_DYN (NSTAGE * STAGE_B)    // 96 KB

#define PPB 8                          // pixels per combine CTA (1 warp/pixel)

// ---------------- scratch (device globals) ----------------
__device__ __half g_Wh[M_GEMM * K_GEMM];      // [m][c]
__device__ __half g_Xh[BATCH * HW * CIN];     // [b][n][c]
// layout: G[b][k][n][o]  (o contiguous), fp16.  75.5 MB
__device__ __half g_Gh[(size_t)BATCH * K2 * HW * COUT];

// ---------------- PTX helpers ----------------
__device__ __forceinline__ uint32_t smem_u32(const void* p) {
    uint32_t a;
    asm("{ .reg .u64 t; cvta.to.shared.u64 t, %1; cvt.u32.u64 %0, t; }" : "=r"(a) : "l"(p));
    return a;
}
#define CP16(dst, src)  asm volatile("cp.async.cg.shared.global [%0], [%1], 16;" :: "r"(dst), "l"(src) : "memory")
#define CP_COMMIT()     asm volatile("cp.async.commit_group;" ::: "memory")
#define CP_WAIT(n)      asm volatile("cp.async.wait_group %0;" :: "n"(n) : "memory")

__device__ __forceinline__ void ldsm_x4(uint32_t* r, uint32_t addr) {
    asm volatile("ldmatrix.sync.aligned.m8n8.x4.shared.b16 {%0,%1,%2,%3}, [%4];"
                 : "=r"(r[0]), "=r"(r[1]), "=r"(r[2]), "=r"(r[3]) : "r"(addr));
}
__device__ __forceinline__ void mma_fp16(float* d, const uint32_t* a, const uint32_t* b) {
    asm volatile("mma.sync.aligned.m16n8k16.row.col.f32.f16.f16.f32 "
                 "{%0,%1,%2,%3}, {%4,%5,%6,%7}, {%8,%9}, {%0,%1,%2,%3};"
                 : "+f"(d[0]), "+f"(d[1]), "+f"(d[2]), "+f"(d[3])
                 : "r"(a[0]), "r"(a[1]), "r"(a[2]), "r"(a[3]), "r"(b[0]), "r"(b[1]));
}
__device__ __forceinline__ uint32_t swz(uint32_t off) { return off ^ ((off >> 3) & 0x70); }

// ---------------------------------------------------------------------------
// Kernel 1: blend (blocks 0..255) ∥ transpose all batches (blocks 256..4351)
// ---------------------------------------------------------------------------
__global__ __launch_bounds__(256) void pre_kernel(const float* __restrict__ weight,
                                                  const float* __restrict__ X) {
    const int tid = threadIdx.x;
    if (blockIdx.x < 256) {
        // ---- circle-blend weights -> fp16, K-major [m][c] ----
        int t = blockIdx.x * 256 + tid;
        int o = t >> 8;
        int c = t & 255;
        const float* wp = weight + ((size_t)(o * CIN + c)) * K2;
        float w0 = wp[0], w1 = wp[1], w2 = wp[2];
        float w3 = wp[3], w4 = wp[4], w5 = wp[5];
        float w6 = wp[6], w7 = wp[7], w8 = wp[8];

        const float A  = 0.7071067811865476f;
        const float Bc = 1.0f - 0.7071067811865476f;

        float t01 = A * w0 + Bc * w1;
        float t34 = A * w3 + Bc * w4;
        float t12 = Bc * w1 + A * w2;
        float t45 = Bc * w4 + A * w5;
        float t67 = A * w6 + Bc * w7;
        float t78 = Bc * w7 + A * w8;

        float nw[K2];
        nw[0] = A * t01 + Bc * t34;  nw[1] = w1;
        nw[2] = A * t12 + Bc * t45;  nw[3] = w3;  nw[4] = w4;  nw[5] = w5;
        nw[6] = Bc * t34 + A * t67;  nw[7] = w7;
        nw[8] = Bc * t45 + A * t78;

#pragma unroll
        for (int k = 0; k < K2; k++)
            g_Wh[(size_t)(k * COUT + o) * K_GEMM + c] = __float2half_rn(nw[k]);
    } else {
        // ---- transpose x[b][c][n] -> Xt[b][n][c] in fp16 ----
        __shared__ float tle[32][33];
        int u  = blockIdx.x - 256;       // 0..4095
        int b  = u >> 10;                // 4 batches
        int r  = u & 1023;               // 1024 tiles per batch
        int n0 = (r & 127) * 32;
        int c0 = (r >> 7) * 32;
        int tx = tid & 31, ty = tid >> 5;

        const float* src = X + ((size_t)b * CIN + c0) * HW + n0;
#pragma unroll
        for (int i = ty; i < 32; i += 8)
            tle[i][tx] = src[(size_t)i * HW + tx];
        __syncthreads();

        __half* dh = g_Xh + ((size_t)b * HW + n0) * CIN + c0;
#pragma unroll
        for (int i = ty; i < 32; i += 8)
            dh[(size_t)i * CIN + tx] = __float2half_rn(tle[tx][i]);
    }
}

// ---------------------------------------------------------------------------
// Kernel 2: fp16 single-pass GEMM, 3-stage cp.async pipeline, one sync/chunk
//   G[b][k][n][o] = sum_c Xh[b][n][c] * Wh[k*256+o][c]   (stored fp16)
// ---------------------------------------------------------------------------
extern __shared__ __align__(1024) unsigned char dsmem[];

__global__ __launch_bounds__(256, 2) void gemm_fp16_kernel() {
    const int tid  = threadIdx.x;
    const int wid  = tid >> 5;
    const int lane = tid & 31;
    const int warp_m = wid >> 2;       // 0..1  (64 n-rows each)
    const int warp_n = wid & 3;        // 0..3  (32 m-cols each)

    const int b  = blockIdx.z;
    const int n0 = blockIdx.x * BM;    // n tile (A rows)
    const int m0 = blockIdx.y * BN;    // m tile (B rows)

    const uint32_t sbase = smem_u32(dsmem);

    const __half* A_g = g_Xh + ((size_t)b * HW + n0) * CIN;
    const __half* B_g = g_Wh + (size_t)m0 * K_GEMM;

    auto copy_chunk = [&](int ch) {
        const uint32_t sb = sbase + (ch % NSTAGE) * STAGE_B;
        const int k0 = ch * BK;
#pragma unroll
        for (int t = 0; t < 4; t++) {
            int u = t * 256 + tid;          // 0..1023
            int r = u >> 3;                 // row 0..127
            int q = u & 7;                  // 16B unit in row
            uint32_t doff = swz((uint32_t)(r * 128 + q * 16));
            CP16(sb + doff,          A_g + (size_t)r * CIN    + k0 + q * 8);
            CP16(sb + TILE_B + doff, B_g + (size_t)r * K_GEMM + k0 + q * 8);
        }
        CP_COMMIT();
    };

    float acc[4][4][4] = {};   // [mf][jj][reg]

    const int arow = warp_m * 64 + (lane & 15);
    const int acol = (lane & 16);
    const int nloc = ((lane >> 4) & 1) * 8 + (lane & 7);
    const int bcol = ((lane >> 3) & 1) * 16;

    copy_chunk(0);
    copy_chunk(1);

#pragma unroll
    for (int ch = 0; ch < NCHUNK; ch++) {
        if (ch < NCHUNK - 1) { CP_WAIT(1); } else { CP_WAIT(0); }
        __syncthreads();   // all warps done reading stage (ch+2)%NSTAGE (= ch-1)

        if (ch + 2 < NCHUNK) copy_chunk(ch + 2);   // overlap copy with compute

        const uint32_t sb = sbase + (ch % NSTAGE) * STAGE_B;
        const uint32_t tA = sb;
        const uint32_t tB = sb + TILE_B;

#pragma unroll
        for (int kf = 0; kf < BK / 16; kf++) {
            uint32_t af[4][4];
#pragma unroll
            for (int mf = 0; mf < 4; mf++) {
                uint32_t off = swz((uint32_t)((arow + mf * 16) * 128 + kf * 32 + acol));
                ldsm_x4(af[mf], tA + off);
            }
            uint32_t bf[4][2];
#pragma unroll
            for (int jp = 0; jp < 2; jp++) {
                uint32_t off = swz((uint32_t)((warp_n * 32 + jp * 16 + nloc) * 128 + kf * 32 + bcol));
                uint32_t rh[4];
                ldsm_x4(rh, tB + off);
                bf[2*jp][0]   = rh[0]; bf[2*jp][1]   = rh[1];
                bf[2*jp+1][0] = rh[2]; bf[2*jp+1][1] = rh[3];
            }
#pragma unroll
            for (int mf = 0; mf < 4; mf++)
#pragma unroll
                for (int jj = 0; jj < 4; jj++)
                    mma_fp16(acc[mf][jj], af[mf], bf[jj]);
        }
    }

    // ---- epilogue: rows = n, cols = o (m within fixed tap k), fp16 stores ----
    const int k_blk = m0 >> 8;          // tap index
    const int o0    = m0 & 255;         // o base (0 or 128)
    __half* Gout = g_Gh + ((size_t)(b * K2 + k_blk)) * HW * COUT;

    const int rbase = n0 + warp_m * 64 + (lane >> 2);          // n
    const int cbase = o0 + warp_n * 32 + (lane & 3) * 2;       // o
#pragma unroll
    for (int mf = 0; mf < 4; mf++) {
#pragma unroll
        for (int jj = 0; jj < 4; jj++) {
            int n = rbase + mf * 16;
            int o = cbase + jj * 8;
            *reinterpret_cast<__half2*>(&Gout[(size_t)n * COUT + o]) =
                __floats2half2_rn(acc[mf][jj][0], acc[mf][jj][1]);
            *reinterpret_cast<__half2*>(&Gout[(size_t)(n + 8) * COUT + o]) =
                __floats2half2_rn(acc[mf][jj][2], acc[mf][jj][3]);
        }
    }
}

// ---------------------------------------------------------------------------
// Kernel 3: combine — coalesced bilinear gather over fp16 G[b][k][n][o]
//   1 warp per pixel, 8 pixels per CTA; lane owns 8 o-channels (16B gathers).
//   launch_bounds(256,5): cap regs at 51 -> 5 CTAs/SM for latency hiding.
// ---------------------------------------------------------------------------
__global__ __launch_bounds__(256, 5) void combine_kernel(
    const float* __restrict__ offset,
    const float* __restrict__ mask,
    const float* __restrict__ bias,
    float* __restrict__ out)
{
    __shared__ int4   s_idx[PPB][K2];
    __shared__ float4 s_cw[PPB][K2];
    __shared__ float  s_out[PPB][COUT];

    const int b    = blockIdx.y;
    const int p0   = blockIdx.x * PPB;
    const int tid  = threadIdx.x;
    const int w    = tid >> 5;
    const int lane = tid & 31;
    const int p    = p0 + w;

    if (lane < K2) {
        const int k  = lane;
        const int py = p >> 6;
        const int px = p & 63;

        float dy = offset[((b * 2 * K2) + 2 * k    ) * HW + p];
        float dx = offset[((b * 2 * K2) + 2 * k + 1) * HW + p];
        float m  = mask[(b * K2 + k) * HW + p];

        float yy = (float)(py - 1 + (k / 3)) + dy;
        float xx = (float)(px - 1 + (k % 3)) + dx;

        float y0f = floorf(yy), x0f = floorf(xx);
        float ly = yy - y0f, lx = xx - x0f;
        float hy = 1.0f - ly, hx = 1.0f - lx;
        int y0 = (int)y0f, x0 = (int)x0f;
        int y1 = y0 + 1,   x1 = x0 + 1;

        bool vy0 = (y0 >= 0) && (y0 < HDIM);
        bool vy1 = (y1 >= 0) && (y1 < HDIM);
        bool vx0 = (x0 >= 0) && (x0 < WDIM);
        bool vx1 = (x1 >= 0) && (x1 < WDIM);

        int cy0 = min(max(y0, 0), HDIM - 1);
        int cy1 = min(max(y1, 0), HDIM - 1);
        int cx0 = min(max(x0, 0), WDIM - 1);
        int cx1 = min(max(x1, 0), WDIM - 1);

        s_idx[w][k] = make_int4(cy0 * WDIM + cx0, cy0 * WDIM + cx1,
                                cy1 * WDIM + cx0, cy1 * WDIM + cx1);
        s_cw[w][k]  = make_float4((vy0 && vx0) ? hy * hx * m : 0.0f,
                                  (vy0 && vx1) ? hy * lx * m : 0.0f,
                                  (vy1 && vx0) ? ly * hx * m : 0.0f,
                                  (vy1 && vx1) ? ly * lx * m : 0.0f);
    }
    __syncwarp();

    const int o8 = lane * 8;
    float acc[8];
    {
        const float4* b4 = reinterpret_cast<const float4*>(bias + o8);
        float4 b0 = b4[0], b1 = b4[1];
        acc[0] = b0.x; acc[1] = b0.y; acc[2] = b0.z; acc[3] = b0.w;
        acc[4] = b1.x; acc[5] = b1.y; acc[6] = b1.z; acc[7] = b1.w;
    }

#pragma unroll
    for (int k = 0; k < K2; k++) {
        int4   id = s_idx[w][k];
        float4 cw = s_cw[w][k];
        const __half* base = g_Gh + ((size_t)(b * K2 + k)) * HW * COUT + o8;

        uint4 v0 = *reinterpret_cast<const uint4*>(base + (size_t)id.x * COUT);
        uint4 v1 = *reinterpret_cast<const uint4*>(base + (size_t)id.y * COUT);
        uint4 v2 = *reinterpret_cast<const uint4*>(base + (size_t)id.z * COUT);
        uint4 v3 = *reinterpret_cast<const uint4*>(base + (size_t)id.w * COUT);

        const __half2* h0 = reinterpret_cast<const __half2*>(&v0);
        const __half2* h1 = reinterpret_cast<const __half2*>(&v1);
        const __half2* h2 = reinterpret_cast<const __half2*>(&v2);
        const __half2* h3 = reinterpret_cast<const __half2*>(&v3);

#pragma unroll
        for (int j = 0; j < 4; j++) {
            float2 a = __half22float2(h0[j]);
            float2 bb = __half22float2(h1[j]);
            float2 c = __half22float2(h2[j]);
            float2 d = __half22float2(h3[j]);
            acc[2*j]   += cw.x * a.x + cw.y * bb.x + cw.z * c.x + cw.w * d.x;
            acc[2*j+1] += cw.x * a.y + cw.y * bb.y + cw.z * c.y + cw.w * d.y;
        }
    }

#pragma unroll
    for (int j = 0; j < 8; j++) s_out[w][o8 + j] = acc[j];
    __syncthreads();

    {
        const int o = tid;
        float4 r0 = make_float4(s_out[0][o], s_out[1][o], s_out[2][o], s_out[3][o]);
        float4 r1 = make_float4(s_out[4][o], s_out[5][o], s_out[6][o], s_out[7][o]);
        float* dst = out + ((size_t)(b * COUT + o)) * HW + p0;
        *reinterpret_cast<float4*>(dst)     = r0;
        *reinterpret_cast<float4*>(dst + 4) = r1;
    }
}

// ---------------------------------------------------------------------------
extern "C" void kernel_launch(void* const* d_in, const int* in_sizes, int n_in,
                              void* d_out, int out_size) {
    const float* x      = (const float*)d_in[0];   // [4,256,64,64]
    const float* offset = (const float*)d_in[1];   // [4,18,64,64]
    const float* mask   = (const float*)d_in[2];   // [4,9,64,64]
    const float* weight = (const float*)d_in[3];   // [256,256,3,3]
    const float* bias   = (const float*)d_in[4];   // [256]
    float* out = (float*)d_out;                    // [4,256,64,64]

    static bool attr_set = false;
    if (!attr_set) {
        cudaFuncSetAttribute(gemm_fp16_kernel,
                             cudaFuncAttributeMaxDynamicSharedMemorySize, SMEM_DYN);
        attr_set = true;
    }

    pre_kernel<<<256 + BATCH * 1024, 256>>>(weight, x);
    gemm_fp16_kernel<<<dim3(HW / BM, M_GEMM / BN, BATCH), 256, SMEM_DYN>>>();
    combine_kernel<<<dim3(HW / PPB, BATCH), 256>>>(offset, mask, bias, out);
}

// round 15
// speedup vs baseline: 1.2223x; 1.0100x over previous
#include <cuda_runtime.h>
#include <cuda_fp16.h>
#include <cstdint>

// ---------------- problem constants ----------------
#define CIN    256
#define COUT   256
#define HDIM   64
#define WDIM   64
#define BATCH  4
#define K2     9
#define HW     4096
#define M_GEMM 2304          // K2 * COUT
#define K_GEMM 256           // CIN

// ---------------- GEMM tiling ----------------
#define BM 128                         // n-tile rows
#define BN 128                         // m-tile cols
#define BK 64                          // fp16 elements per chunk (128B rows)
#define NCHUNK (K_GEMM / BK)           // 4
#define NSTAGE 3
#define TILE_B (BM * BK * 2)           // 16384 bytes per operand tile
#define STAGE_B (2 * TILE_B)           // A, B = 32 KB
#define SMEM_DYN (NSTAGE * STAGE_B)    // 96 KB

#define PPB 8                          // pixels per combine CTA (1 warp/pixel)

// ---------------- scratch (device globals) ----------------
__device__ __half g_Wh[M_GEMM * K_GEMM];      // [m][c]
__device__ __half g_Xh[BATCH * HW * CIN];     // [b][n][c]
// layout: G[b][k][n][o]  (o contiguous), fp16.  75.5 MB
__device__ __half g_Gh[(size_t)BATCH * K2 * HW * COUT];

// ---------------- PTX helpers ----------------
__device__ __forceinline__ uint32_t smem_u32(const void* p) {
    uint32_t a;
    asm("{ .reg .u64 t; cvta.to.shared.u64 t, %1; cvt.u32.u64 %0, t; }" : "=r"(a) : "l"(p));
    return a;
}
#define CP16(dst, src)  asm volatile("cp.async.cg.shared.global [%0], [%1], 16;" :: "r"(dst), "l"(src) : "memory")
#define CP_COMMIT()     asm volatile("cp.async.commit_group;" ::: "memory")
#define CP_WAIT(n)      asm volatile("cp.async.wait_group %0;" :: "n"(n) : "memory")

__device__ __forceinline__ void ldsm_x4(uint32_t* r, uint32_t addr) {
    asm volatile("ldmatrix.sync.aligned.m8n8.x4.shared.b16 {%0,%1,%2,%3}, [%4];"
                 : "=r"(r[0]), "=r"(r[1]), "=r"(r[2]), "=r"(r[3]) : "r"(addr));
}
__device__ __forceinline__ void mma_fp16(float* d, const uint32_t* a, const uint32_t* b) {
    asm volatile("mma.sync.aligned.m16n8k16.row.col.f32.f16.f16.f32 "
                 "{%0,%1,%2,%3}, {%4,%5,%6,%7}, {%8,%9}, {%0,%1,%2,%3};"
                 : "+f"(d[0]), "+f"(d[1]), "+f"(d[2]), "+f"(d[3])
                 : "r"(a[0]), "r"(a[1]), "r"(a[2]), "r"(a[3]), "r"(b[0]), "r"(b[1]));
}
__device__ __forceinline__ uint32_t swz(uint32_t off) { return off ^ ((off >> 3) & 0x70); }

// ---------------------------------------------------------------------------
// Kernel 1: blend (blocks 0..255) ∥ vectorized transpose (blocks 256..1279)
//   Transpose: 64x64 tile; float4 loads, smem s[64][65], uint4 fp16 stores.
// ---------------------------------------------------------------------------
__global__ __launch_bounds__(256) void pre_kernel(const float* __restrict__ weight,
                                                  const float* __restrict__ X) {
    const int tid = threadIdx.x;
    if (blockIdx.x < 256) {
        // ---- circle-blend weights -> fp16, K-major [m][c] ----
        int t = blockIdx.x * 256 + tid;
        int o = t >> 8;
        int c = t & 255;
        const float* wp = weight + ((size_t)(o * CIN + c)) * K2;
        float w0 = wp[0], w1 = wp[1], w2 = wp[2];
        float w3 = wp[3], w4 = wp[4], w5 = wp[5];
        float w6 = wp[6], w7 = wp[7], w8 = wp[8];

        const float A  = 0.7071067811865476f;
        const float Bc = 1.0f - 0.7071067811865476f;

        float t01 = A * w0 + Bc * w1;
        float t34 = A * w3 + Bc * w4;
        float t12 = Bc * w1 + A * w2;
        float t45 = Bc * w4 + A * w5;
        float t67 = A * w6 + Bc * w7;
        float t78 = Bc * w7 + A * w8;

        float nw[K2];
        nw[0] = A * t01 + Bc * t34;  nw[1] = w1;
        nw[2] = A * t12 + Bc * t45;  nw[3] = w3;  nw[4] = w4;  nw[5] = w5;
        nw[6] = Bc * t34 + A * t67;  nw[7] = w7;
        nw[8] = Bc * t45 + A * t78;

#pragma unroll
        for (int k = 0; k < K2; k++)
            g_Wh[(size_t)(k * COUT + o) * K_GEMM + c] = __float2half_rn(nw[k]);
    } else {
        // ---- transpose x[b][c][n] -> Xt[b][n][c] in fp16, 64x64 tile ----
        __shared__ float s[64][65];
        int u  = blockIdx.x - 256;       // 0..1023
        int b  = u >> 8;                 // 4 batches (256 tiles each)
        int r  = u & 255;
        int n0 = (r & 63) * 64;          // 64 n-tiles
        int c0 = (r >> 6) * 64;          // 4 c-tiles

        // load: thread covers 4 c-rows x 4 n (float4)
        const int c  = tid >> 4;         // 0..15 (+16i)
        const int n4 = (tid & 15) * 4;   // 0..60
        const float* src = X + ((size_t)b * CIN + c0) * HW + n0;
#pragma unroll
        for (int i = 0; i < 4; i++) {
            int cc = c + i * 16;
            float4 v = *reinterpret_cast<const float4*>(src + (size_t)cc * HW + n4);
            s[n4 + 0][cc] = v.x;
            s[n4 + 1][cc] = v.y;
            s[n4 + 2][cc] = v.z;
            s[n4 + 3][cc] = v.w;
        }
        __syncthreads();

        // store: thread writes 16 contiguous c (2 x uint4 fp16) for one n-row
        const int n  = tid >> 2;         // 0..63
        const int cs = (tid & 3) * 16;   // 0..48
        __half hbuf[16];
#pragma unroll
        for (int j = 0; j < 16; j++)
            hbuf[j] = __float2half_rn(s[n][cs + j]);
        __half* dh = g_Xh + ((size_t)b * HW + n0 + n) * CIN + c0 + cs;
        *reinterpret_cast<uint4*>(dh)     = *reinterpret_cast<uint4*>(hbuf);
        *reinterpret_cast<uint4*>(dh + 8) = *reinterpret_cast<uint4*>(hbuf + 8);
    }
}

// ---------------------------------------------------------------------------
// Kernel 2: fp16 single-pass GEMM, 3-stage cp.async pipeline, one sync/chunk
//   G[b][k][n][o] = sum_c Xh[b][n][c] * Wh[k*256+o][c]   (stored fp16)
// ---------------------------------------------------------------------------
extern __shared__ __align__(1024) unsigned char dsmem[];

__global__ __launch_bounds__(256, 2) void gemm_fp16_kernel() {
    const int tid  = threadIdx.x;
    const int wid  = tid >> 5;
    const int lane = tid & 31;
    const int warp_m = wid >> 2;       // 0..1  (64 n-rows each)
    const int warp_n = wid & 3;        // 0..3  (32 m-cols each)

    const int b  = blockIdx.z;
    const int n0 = blockIdx.x * BM;    // n tile (A rows)
    const int m0 = blockIdx.y * BN;    // m tile (B rows)

    const uint32_t sbase = smem_u32(dsmem);

    const __half* A_g = g_Xh + ((size_t)b * HW + n0) * CIN;
    const __half* B_g = g_Wh + (size_t)m0 * K_GEMM;

    auto copy_chunk = [&](int ch) {
        const uint32_t sb = sbase + (ch % NSTAGE) * STAGE_B;
        const int k0 = ch * BK;
#pragma unroll
        for (int t = 0; t < 4; t++) {
            int u = t * 256 + tid;          // 0..1023
            int r = u >> 3;                 // row 0..127
            int q = u & 7;                  // 16B unit in row
            uint32_t doff = swz((uint32_t)(r * 128 + q * 16));
            CP16(sb + doff,          A_g + (size_t)r * CIN    + k0 + q * 8);
            CP16(sb + TILE_B + doff, B_g + (size_t)r * K_GEMM + k0 + q * 8);
        }
        CP_COMMIT();
    };

    float acc[4][4][4] = {};   // [mf][jj][reg]

    const int arow = warp_m * 64 + (lane & 15);
    const int acol = (lane & 16);
    const int nloc = ((lane >> 4) & 1) * 8 + (lane & 7);
    const int bcol = ((lane >> 3) & 1) * 16;

    copy_chunk(0);
    copy_chunk(1);

#pragma unroll
    for (int ch = 0; ch < NCHUNK; ch++) {
        if (ch < NCHUNK - 1) { CP_WAIT(1); } else { CP_WAIT(0); }
        __syncthreads();   // all warps done reading stage (ch+2)%NSTAGE (= ch-1)

        if (ch + 2 < NCHUNK) copy_chunk(ch + 2);   // overlap copy with compute

        const uint32_t sb = sbase + (ch % NSTAGE) * STAGE_B;
        const uint32_t tA = sb;
        const uint32_t tB = sb + TILE_B;

#pragma unroll
        for (int kf = 0; kf < BK / 16; kf++) {
            uint32_t af[4][4];
#pragma unroll
            for (int mf = 0; mf < 4; mf++) {
                uint32_t off = swz((uint32_t)((arow + mf * 16) * 128 + kf * 32 + acol));
                ldsm_x4(af[mf], tA + off);
            }
            uint32_t bf[4][2];
#pragma unroll
            for (int jp = 0; jp < 2; jp++) {
                uint32_t off = swz((uint32_t)((warp_n * 32 + jp * 16 + nloc) * 128 + kf * 32 + bcol));
                uint32_t rh[4];
                ldsm_x4(rh, tB + off);
                bf[2*jp][0]   = rh[0]; bf[2*jp][1]   = rh[1];
                bf[2*jp+1][0] = rh[2]; bf[2*jp+1][1] = rh[3];
            }
#pragma unroll
            for (int mf = 0; mf < 4; mf++)
#pragma unroll
                for (int jj = 0; jj < 4; jj++)
                    mma_fp16(acc[mf][jj], af[mf], bf[jj]);
        }
    }

    // ---- epilogue: rows = n, cols = o (m within fixed tap k), fp16 stores ----
    const int k_blk = m0 >> 8;          // tap index
    const int o0    = m0 & 255;         // o base (0 or 128)
    __half* Gout = g_Gh + ((size_t)(b * K2 + k_blk)) * HW * COUT;

    const int rbase = n0 + warp_m * 64 + (lane >> 2);          // n
    const int cbase = o0 + warp_n * 32 + (lane & 3) * 2;       // o
#pragma unroll
    for (int mf = 0; mf < 4; mf++) {
#pragma unroll
        for (int jj = 0; jj < 4; jj++) {
            int n = rbase + mf * 16;
            int o = cbase + jj * 8;
            *reinterpret_cast<__half2*>(&Gout[(size_t)n * COUT + o]) =
                __floats2half2_rn(acc[mf][jj][0], acc[mf][jj][1]);
            *reinterpret_cast<__half2*>(&Gout[(size_t)(n + 8) * COUT + o]) =
                __floats2half2_rn(acc[mf][jj][2], acc[mf][jj][3]);
        }
    }
}

// ---------------------------------------------------------------------------
// Kernel 3: combine — coalesced bilinear gather over fp16 G[b][k][n][o]
//   1 warp per pixel, 8 pixels per CTA; lane owns 8 o-channels (16B gathers).
//   launch_bounds(256,5): cap regs at 51 -> 5 CTAs/SM for latency hiding.
// ---------------------------------------------------------------------------
__global__ __launch_bounds__(256, 5) void combine_kernel(
    const float* __restrict__ offset,
    const float* __restrict__ mask,
    const float* __restrict__ bias,
    float* __restrict__ out)
{
    __shared__ int4   s_idx[PPB][K2];
    __shared__ float4 s_cw[PPB][K2];
    __shared__ float  s_out[PPB][COUT];

    const int b    = blockIdx.y;
    const int p0   = blockIdx.x * PPB;
    const int tid  = threadIdx.x;
    const int w    = tid >> 5;
    const int lane = tid & 31;
    const int p    = p0 + w;

    if (lane < K2) {
        const int k  = lane;
        const int py = p >> 6;
        const int px = p & 63;

        float dy = offset[((b * 2 * K2) + 2 * k    ) * HW + p];
        float dx = offset[((b * 2 * K2) + 2 * k + 1) * HW + p];
        float m  = mask[(b * K2 + k) * HW + p];

        float yy = (float)(py - 1 + (k / 3)) + dy;
        float xx = (float)(px - 1 + (k % 3)) + dx;

        float y0f = floorf(yy), x0f = floorf(xx);
        float ly = yy - y0f, lx = xx - x0f;
        float hy = 1.0f - ly, hx = 1.0f - lx;
        int y0 = (int)y0f, x0 = (int)x0f;
        int y1 = y0 + 1,   x1 = x0 + 1;

        bool vy0 = (y0 >= 0) && (y0 < HDIM);
        bool vy1 = (y1 >= 0) && (y1 < HDIM);
        bool vx0 = (x0 >= 0) && (x0 < WDIM);
        bool vx1 = (x1 >= 0) && (x1 < WDIM);

        int cy0 = min(max(y0, 0), HDIM - 1);
        int cy1 = min(max(y1, 0), HDIM - 1);
        int cx0 = min(max(x0, 0), WDIM - 1);
        int cx1 = min(max(x1, 0), WDIM - 1);

        s_idx[w][k] = make_int4(cy0 * WDIM + cx0, cy0 * WDIM + cx1,
                                cy1 * WDIM + cx0, cy1 * WDIM + cx1);
        s_cw[w][k]  = make_float4((vy0 && vx0) ? hy * hx * m : 0.0f,
                                  (vy0 && vx1) ? hy * lx * m : 0.0f,
                                  (vy1 && vx0) ? ly * hx * m : 0.0f,
                                  (vy1 && vx1) ? ly * lx * m : 0.0f);
    }
    __syncwarp();

    const int o8 = lane * 8;
    float acc[8];
    {
        const float4* b4 = reinterpret_cast<const float4*>(bias + o8);
        float4 b0 = b4[0], b1 = b4[1];
        acc[0] = b0.x; acc[1] = b0.y; acc[2] = b0.z; acc[3] = b0.w;
        acc[4] = b1.x; acc[5] = b1.y; acc[6] = b1.z; acc[7] = b1.w;
    }

#pragma unroll
    for (int k = 0; k < K2; k++) {
        int4   id = s_idx[w][k];
        float4 cw = s_cw[w][k];
        const __half* base = g_Gh + ((size_t)(b * K2 + k)) * HW * COUT + o8;

        uint4 v0 = *reinterpret_cast<const uint4*>(base + (size_t)id.x * COUT);
        uint4 v1 = *reinterpret_cast<const uint4*>(base + (size_t)id.y * COUT);
        uint4 v2 = *reinterpret_cast<const uint4*>(base + (size_t)id.z * COUT);
        uint4 v3 = *reinterpret_cast<const uint4*>(base + (size_t)id.w * COUT);

        const __half2* h0 = reinterpret_cast<const __half2*>(&v0);
        const __half2* h1 = reinterpret_cast<const __half2*>(&v1);
        const __half2* h2 = reinterpret_cast<const __half2*>(&v2);
        const __half2* h3 = reinterpret_cast<const __half2*>(&v3);

#pragma unroll
        for (int j = 0; j < 4; j++) {
            float2 a = __half22float2(h0[j]);
            float2 bb = __half22float2(h1[j]);
            float2 c = __half22float2(h2[j]);
            float2 d = __half22float2(h3[j]);
            acc[2*j]   += cw.x * a.x + cw.y * bb.x + cw.z * c.x + cw.w * d.x;
            acc[2*j+1] += cw.x * a.y + cw.y * bb.y + cw.z * c.y + cw.w * d.y;
        }
    }

#pragma unroll
    for (int j = 0; j < 8; j++) s_out[w][o8 + j] = acc[j];
    __syncthreads();

    {
        const int o = tid;
        float4 r0 = make_float4(s_out[0][o], s_out[1][o], s_out[2][o], s_out[3][o]);
        float4 r1 = make_float4(s_out[4][o], s_out[5][o], s_out[6][o], s_out[7][o]);
        float* dst = out + ((size_t)(b * COUT + o)) * HW + p0;
        *reinterpret_cast<float4*>(dst)     = r0;
        *reinterpret_cast<float4*>(dst + 4) = r1;
    }
}

// ---------------------------------------------------------------------------
extern "C" void kernel_launch(void* const* d_in, const int* in_sizes, int n_in,
                              void* d_out, int out_size) {
    const float* x      = (const float*)d_in[0];   // [4,256,64,64]
    const float* offset = (const float*)d_in[1];   // [4,18,64,64]
    const float* mask   = (const float*)d_in[2];   // [4,9,64,64]
    const float* weight = (const float*)d_in[3];   // [256,256,3,3]
    const float* bias   = (const float*)d_in[4];   // [256]
    float* out = (float*)d_out;                    // [4,256,64,64]

    static bool attr_set = false;
    if (!attr_set) {
        cudaFuncSetAttribute(gemm_fp16_kernel,
                             cudaFuncAttributeMaxDynamicSharedMemorySize, SMEM_DYN);
        attr_set = true;
    }

    pre_kernel<<<256 + BATCH * 256, 256>>>(weight, x);
    gemm_fp16_kernel<<<dim3(HW / BM, M_GEMM / BN, BATCH), 256, SMEM_DYN>>>();
    combine_kernel<<<dim3(HW / PPB, BATCH), 256>>>(offset, mask, bias, out);
}

// round 16
// speedup vs baseline: 1.2239x; 1.0013x over previous
#include <cuda_runtime.h>
#include <cuda_fp16.h>
#include <cstdint>

// ---------------- problem constants ----------------
#define CIN    256
#define COUT   256
#define HDIM   64
#define WDIM   64
#define BATCH  4
#define K2     9
#define HW     4096
#define M_GEMM 2304          // K2 * COUT
#define K_GEMM 256           // CIN

// ---------------- GEMM tiling ----------------
#define BM 128                         // n-tile rows
#define BN 128                         // m-tile cols
#define BK 64                          // fp16 elements per chunk (128B rows)
#define NCHUNK (K_GEMM / BK)           // 4
#define NSTAGE 3
#define TILE_B (BM * BK * 2)           // 16384 bytes per operand tile
#define STAGE_B (2 * TILE_B)           // A, B = 32 KB
#define SMEM_DYN (NSTAGE * STAGE_B)    // 96 KB

#define PPB 8                          // pixels per combine CTA (1 warp/pixel)

// ---------------- scratch (device globals) ----------------
__device__ __half g_Wh[M_GEMM * K_GEMM];      // [m][c]
__device__ __half g_Xh[BATCH * HW * CIN];     // [b][n][c]
// layout: G[b][k][n][o]  (o contiguous), fp16.  75.5 MB
__device__ __half g_Gh[(size_t)BATCH * K2 * HW * COUT];

// ---------------- PTX helpers ----------------
__device__ __forceinline__ uint32_t smem_u32(const void* p) {
    uint32_t a;
    asm("{ .reg .u64 t; cvta.to.shared.u64 t, %1; cvt.u32.u64 %0, t; }" : "=r"(a) : "l"(p));
    return a;
}
#define CP16(dst, src)  asm volatile("cp.async.cg.shared.global [%0], [%1], 16;" :: "r"(dst), "l"(src) : "memory")
#define CP_COMMIT()     asm volatile("cp.async.commit_group;" ::: "memory")
#define CP_WAIT(n)      asm volatile("cp.async.wait_group %0;" :: "n"(n) : "memory")

__device__ __forceinline__ void ldsm_x4(uint32_t* r, uint32_t addr) {
    asm volatile("ldmatrix.sync.aligned.m8n8.x4.shared.b16 {%0,%1,%2,%3}, [%4];"
                 : "=r"(r[0]), "=r"(r[1]), "=r"(r[2]), "=r"(r[3]) : "r"(addr));
}
__device__ __forceinline__ void mma_fp16(float* d, const uint32_t* a, const uint32_t* b) {
    asm volatile("mma.sync.aligned.m16n8k16.row.col.f32.f16.f16.f32 "
                 "{%0,%1,%2,%3}, {%4,%5,%6,%7}, {%8,%9}, {%0,%1,%2,%3};"
                 : "+f"(d[0]), "+f"(d[1]), "+f"(d[2]), "+f"(d[3])
                 : "r"(a[0]), "r"(a[1]), "r"(a[2]), "r"(a[3]), "r"(b[0]), "r"(b[1]));
}
__device__ __forceinline__ uint32_t swz(uint32_t off) { return off ^ ((off >> 3) & 0x70); }

// ---------------------------------------------------------------------------
// Kernel 1: blend (blocks 0..255) ∥ transpose all batches (blocks 256..4351)
//   Transpose: 32x32 tiles (4096 CTAs) — best measured variant (R12, 8.8us).
// ---------------------------------------------------------------------------
__global__ __launch_bounds__(256) void pre_kernel(const float* __restrict__ weight,
                                                  const float* __restrict__ X) {
    const int tid = threadIdx.x;
    if (blockIdx.x < 256) {
        // ---- circle-blend weights -> fp16, K-major [m][c] ----
        int t = blockIdx.x * 256 + tid;
        int o = t >> 8;
        int c = t & 255;
        const float* wp = weight + ((size_t)(o * CIN + c)) * K2;
        float w0 = wp[0], w1 = wp[1], w2 = wp[2];
        float w3 = wp[3], w4 = wp[4], w5 = wp[5];
        float w6 = wp[6], w7 = wp[7], w8 = wp[8];

        const float A  = 0.7071067811865476f;
        const float Bc = 1.0f - 0.7071067811865476f;

        float t01 = A * w0 + Bc * w1;
        float t34 = A * w3 + Bc * w4;
        float t12 = Bc * w1 + A * w2;
        float t45 = Bc * w4 + A * w5;
        float t67 = A * w6 + Bc * w7;
        float t78 = Bc * w7 + A * w8;

        float nw[K2];
        nw[0] = A * t01 + Bc * t34;  nw[1] = w1;
        nw[2] = A * t12 + Bc * t45;  nw[3] = w3;  nw[4] = w4;  nw[5] = w5;
        nw[6] = Bc * t34 + A * t67;  nw[7] = w7;
        nw[8] = Bc * t45 + A * t78;

#pragma unroll
        for (int k = 0; k < K2; k++)
            g_Wh[(size_t)(k * COUT + o) * K_GEMM + c] = __float2half_rn(nw[k]);
    } else {
        // ---- transpose x[b][c][n] -> Xt[b][n][c] in fp16 ----
        __shared__ float tle[32][33];
        int u  = blockIdx.x - 256;       // 0..4095
        int b  = u >> 10;                // 4 batches
        int r  = u & 1023;               // 1024 tiles per batch
        int n0 = (r & 127) * 32;
        int c0 = (r >> 7) * 32;
        int tx = tid & 31, ty = tid >> 5;

        const float* src = X + ((size_t)b * CIN + c0) * HW + n0;
#pragma unroll
        for (int i = ty; i < 32; i += 8)
            tle[i][tx] = src[(size_t)i * HW + tx];
        __syncthreads();

        __half* dh = g_Xh + ((size_t)b * HW + n0) * CIN + c0;
#pragma unroll
        for (int i = ty; i < 32; i += 8)
            dh[(size_t)i * CIN + tx] = __float2half_rn(tle[tx][i]);
    }
}

// ---------------------------------------------------------------------------
// Kernel 2: fp16 single-pass GEMM, 3-stage cp.async pipeline, one sync/chunk
//   G[b][k][n][o] = sum_c Xh[b][n][c] * Wh[k*256+o][c]   (stored fp16)
// ---------------------------------------------------------------------------
extern __shared__ __align__(1024) unsigned char dsmem[];

__global__ __launch_bounds__(256, 2) void gemm_fp16_kernel() {
    const int tid  = threadIdx.x;
    const int wid  = tid >> 5;
    const int lane = tid & 31;
    const int warp_m = wid >> 2;       // 0..1  (64 n-rows each)
    const int warp_n = wid & 3;        // 0..3  (32 m-cols each)

    const int b  = blockIdx.z;
    const int n0 = blockIdx.x * BM;    // n tile (A rows)
    const int m0 = blockIdx.y * BN;    // m tile (B rows)

    const uint32_t sbase = smem_u32(dsmem);

    const __half* A_g = g_Xh + ((size_t)b * HW + n0) * CIN;
    const __half* B_g = g_Wh + (size_t)m0 * K_GEMM;

    auto copy_chunk = [&](int ch) {
        const uint32_t sb = sbase + (ch % NSTAGE) * STAGE_B;
        const int k0 = ch * BK;
#pragma unroll
        for (int t = 0; t < 4; t++) {
            int u = t * 256 + tid;          // 0..1023
            int r = u >> 3;                 // row 0..127
            int q = u & 7;                  // 16B unit in row
            uint32_t doff = swz((uint32_t)(r * 128 + q * 16));
            CP16(sb + doff,          A_g + (size_t)r * CIN    + k0 + q * 8);
            CP16(sb + TILE_B + doff, B_g + (size_t)r * K_GEMM + k0 + q * 8);
        }
        CP_COMMIT();
    };

    float acc[4][4][4] = {};   // [mf][jj][reg]

    const int arow = warp_m * 64 + (lane & 15);
    const int acol = (lane & 16);
    const int nloc = ((lane >> 4) & 1) * 8 + (lane & 7);
    const int bcol = ((lane >> 3) & 1) * 16;

    copy_chunk(0);
    copy_chunk(1);

#pragma unroll
    for (int ch = 0; ch < NCHUNK; ch++) {
        if (ch < NCHUNK - 1) { CP_WAIT(1); } else { CP_WAIT(0); }
        __syncthreads();   // all warps done reading stage (ch+2)%NSTAGE (= ch-1)

        if (ch + 2 < NCHUNK) copy_chunk(ch + 2);   // overlap copy with compute

        const uint32_t sb = sbase + (ch % NSTAGE) * STAGE_B;
        const uint32_t tA = sb;
        const uint32_t tB = sb + TILE_B;

#pragma unroll
        for (int kf = 0; kf < BK / 16; kf++) {
            uint32_t af[4][4];
#pragma unroll
            for (int mf = 0; mf < 4; mf++) {
                uint32_t off = swz((uint32_t)((arow + mf * 16) * 128 + kf * 32 + acol));
                ldsm_x4(af[mf], tA + off);
            }
            uint32_t bf[4][2];
#pragma unroll
            for (int jp = 0; jp < 2; jp++) {
                uint32_t off = swz((uint32_t)((warp_n * 32 + jp * 16 + nloc) * 128 + kf * 32 + bcol));
                uint32_t rh[4];
                ldsm_x4(rh, tB + off);
                bf[2*jp][0]   = rh[0]; bf[2*jp][1]   = rh[1];
                bf[2*jp+1][0] = rh[2]; bf[2*jp+1][1] = rh[3];
            }
#pragma unroll
            for (int mf = 0; mf < 4; mf++)
#pragma unroll
                for (int jj = 0; jj < 4; jj++)
                    mma_fp16(acc[mf][jj], af[mf], bf[jj]);
        }
    }

    // ---- epilogue: rows = n, cols = o (m within fixed tap k), fp16 stores ----
    const int k_blk = m0 >> 8;          // tap index
    const int o0    = m0 & 255;         // o base (0 or 128)
    __half* Gout = g_Gh + ((size_t)(b * K2 + k_blk)) * HW * COUT;

    const int rbase = n0 + warp_m * 64 + (lane >> 2);          // n
    const int cbase = o0 + warp_n * 32 + (lane & 3) * 2;       // o
#pragma unroll
    for (int mf = 0; mf < 4; mf++) {
#pragma unroll
        for (int jj = 0; jj < 4; jj++) {
            int n = rbase + mf * 16;
            int o = cbase + jj * 8;
            *reinterpret_cast<__half2*>(&Gout[(size_t)n * COUT + o]) =
                __floats2half2_rn(acc[mf][jj][0], acc[mf][jj][1]);
            *reinterpret_cast<__half2*>(&Gout[(size_t)(n + 8) * COUT + o]) =
                __floats2half2_rn(acc[mf][jj][2], acc[mf][jj][3]);
        }
    }
}

// ---------------------------------------------------------------------------
// Kernel 3: combine — coalesced bilinear gather over fp16 G[b][k][n][o]
//   1 warp per pixel, 8 pixels per CTA; lane owns 8 o-channels (16B gathers).
//   launch_bounds(256,6): cap regs at 42 -> 6 CTAs/SM for latency hiding.
// ---------------------------------------------------------------------------
__global__ __launch_bounds__(256, 6) void combine_kernel(
    const float* __restrict__ offset,
    const float* __restrict__ mask,
    const float* __restrict__ bias,
    float* __restrict__ out)
{
    __shared__ int4   s_idx[PPB][K2];
    __shared__ float4 s_cw[PPB][K2];
    __shared__ float  s_out[PPB][COUT];

    const int b    = blockIdx.y;
    const int p0   = blockIdx.x * PPB;
    const int tid  = threadIdx.x;
    const int w    = tid >> 5;
    const int lane = tid & 31;
    const int p    = p0 + w;

    if (lane < K2) {
        const int k  = lane;
        const int py = p >> 6;
        const int px = p & 63;

        float dy = offset[((b * 2 * K2) + 2 * k    ) * HW + p];
        float dx = offset[((b * 2 * K2) + 2 * k + 1) * HW + p];
        float m  = mask[(b * K2 + k) * HW + p];

        float yy = (float)(py - 1 + (k / 3)) + dy;
        float xx = (float)(px - 1 + (k % 3)) + dx;

        float y0f = floorf(yy), x0f = floorf(xx);
        float ly = yy - y0f, lx = xx - x0f;
        float hy = 1.0f - ly, hx = 1.0f - lx;
        int y0 = (int)y0f, x0 = (int)x0f;
        int y1 = y0 + 1,   x1 = x0 + 1;

        bool vy0 = (y0 >= 0) && (y0 < HDIM);
        bool vy1 = (y1 >= 0) && (y1 < HDIM);
        bool vx0 = (x0 >= 0) && (x0 < WDIM);
        bool vx1 = (x1 >= 0) && (x1 < WDIM);

        int cy0 = min(max(y0, 0), HDIM - 1);
        int cy1 = min(max(y1, 0), HDIM - 1);
        int cx0 = min(max(x0, 0), WDIM - 1);
        int cx1 = min(max(x1, 0), WDIM - 1);

        s_idx[w][k] = make_int4(cy0 * WDIM + cx0, cy0 * WDIM + cx1,
                                cy1 * WDIM + cx0, cy1 * WDIM + cx1);
        s_cw[w][k]  = make_float4((vy0 && vx0) ? hy * hx * m : 0.0f,
                                  (vy0 && vx1) ? hy * lx * m : 0.0f,
                                  (vy1 && vx0) ? ly * hx * m : 0.0f,
                                  (vy1 && vx1) ? ly * lx * m : 0.0f);
    }
    __syncwarp();

    const int o8 = lane * 8;
    float acc[8];
    {
        const float4* b4 = reinterpret_cast<const float4*>(bias + o8);
        float4 b0 = b4[0], b1 = b4[1];
        acc[0] = b0.x; acc[1] = b0.y; acc[2] = b0.z; acc[3] = b0.w;
        acc[4] = b1.x; acc[5] = b1.y; acc[6] = b1.z; acc[7] = b1.w;
    }

#pragma unroll
    for (int k = 0; k < K2; k++) {
        int4   id = s_idx[w][k];
        float4 cw = s_cw[w][k];
        const __half* base = g_Gh + ((size_t)(b * K2 + k)) * HW * COUT + o8;

        uint4 v0 = *reinterpret_cast<const uint4*>(base + (size_t)id.x * COUT);
        uint4 v1 = *reinterpret_cast<const uint4*>(base + (size_t)id.y * COUT);
        uint4 v2 = *reinterpret_cast<const uint4*>(base + (size_t)id.z * COUT);
        uint4 v3 = *reinterpret_cast<const uint4*>(base + (size_t)id.w * COUT);

        const __half2* h0 = reinterpret_cast<const __half2*>(&v0);
        const __half2* h1 = reinterpret_cast<const __half2*>(&v1);
        const __half2* h2 = reinterpret_cast<const __half2*>(&v2);
        const __half2* h3 = reinterpret_cast<const __half2*>(&v3);

#pragma unroll
        for (int j = 0; j < 4; j++) {
            float2 a = __half22float2(h0[j]);
            float2 bb = __half22float2(h1[j]);
            float2 c = __half22float2(h2[j]);
            float2 d = __half22float2(h3[j]);
            acc[2*j]   += cw.x * a.x + cw.y * bb.x + cw.z * c.x + cw.w * d.x;
            acc[2*j+1] += cw.x * a.y + cw.y * bb.y + cw.z * c.y + cw.w * d.y;
        }
    }

#pragma unroll
    for (int j = 0; j < 8; j++) s_out[w][o8 + j] = acc[j];
    __syncthreads();

    {
        const int o = tid;
        float4 r0 = make_float4(s_out[0][o], s_out[1][o], s_out[2][o], s_out[3][o]);
        float4 r1 = make_float4(s_out[4][o], s_out[5][o], s_out[6][o], s_out[7][o]);
        float* dst = out + ((size_t)(b * COUT + o)) * HW + p0;
        *reinterpret_cast<float4*>(dst)     = r0;
        *reinterpret_cast<float4*>(dst + 4) = r1;
    }
}

// ---------------------------------------------------------------------------
extern "C" void kernel_launch(void* const* d_in, const int* in_sizes, int n_in,
                              void* d_out, int out_size) {
    const float* x      = (const float*)d_in[0];   // [4,256,64,64]
    const float* offset = (const float*)d_in[1];   // [4,18,64,64]
    const float* mask   = (const float*)d_in[2];   // [4,9,64,64]
    const float* weight = (const float*)d_in[3];   // [256,256,3,3]
    const float* bias   = (const float*)d_in[4];   // [256]
    float* out = (float*)d_out;                    // [4,256,64,64]

    static bool attr_set = false;
    if (!attr_set) {
        cudaFuncSetAttribute(gemm_fp16_kernel,
                             cudaFuncAttributeMaxDynamicSharedMemorySize, SMEM_DYN);
        attr_set = true;
    }

    pre_kernel<<<256 + BATCH * 1024, 256>>>(weight, x);
    gemm_fp16_kernel<<<dim3(HW / BM, M_GEMM / BN, BATCH), 256, SMEM_DYN>>>();
    combine_kernel<<<dim3(HW / PPB, BATCH), 256>>>(offset, mask, bias, out);
}

// round 17
// speedup vs baseline: 1.2275x; 1.0029x over previous
#include <cuda_runtime.h>
#include <cuda_fp16.h>
#include <cstdint>

// ---------------- problem constants ----------------
#define CIN    256
#define COUT   256
#define HDIM   64
#define WDIM   64
#define BATCH  4
#define K2     9
#define HW     4096
#define M_GEMM 2304          // K2 * COUT
#define K_GEMM 256           // CIN

// ---------------- GEMM tiling ----------------
#define BM 128                         // n-tile rows
#define BN 128                         // m-tile cols
#define BK 64                          // fp16 elements per chunk (128B rows)
#define NCHUNK (K_GEMM / BK)           // 4
#define NSTAGE 3
#define TILE_B (BM * BK * 2)           // 16384 bytes per operand tile
#define STAGE_B (2 * TILE_B)           // A, B = 32 KB
#define SMEM_DYN (NSTAGE * STAGE_B)    // 96 KB

#define PPB 8                          // pixels per combine CTA (1 warp/pixel)

// ---------------- scratch (device globals) ----------------
__device__ __half g_Wh[M_GEMM * K_GEMM];      // [m][c]
__device__ __half g_Xh[BATCH * HW * CIN];     // [b][n][c]
// layout: G[b][k][n][o]  (o contiguous), fp16.  75.5 MB
__device__ __half g_Gh[(size_t)BATCH * K2 * HW * COUT];

// ---------------- PTX helpers ----------------
__device__ __forceinline__ uint32_t smem_u32(const void* p) {
    uint32_t a;
    asm("{ .reg .u64 t; cvta.to.shared.u64 t, %1; cvt.u32.u64 %0, t; }" : "=r"(a) : "l"(p));
    return a;
}
#define CP16(dst, src)  asm volatile("cp.async.cg.shared.global [%0], [%1], 16;" :: "r"(dst), "l"(src) : "memory")
#define CP_COMMIT()     asm volatile("cp.async.commit_group;" ::: "memory")
#define CP_WAIT(n)      asm volatile("cp.async.wait_group %0;" :: "n"(n) : "memory")

__device__ __forceinline__ void ldsm_x4(uint32_t* r, uint32_t addr) {
    asm volatile("ldmatrix.sync.aligned.m8n8.x4.shared.b16 {%0,%1,%2,%3}, [%4];"
                 : "=r"(r[0]), "=r"(r[1]), "=r"(r[2]), "=r"(r[3]) : "r"(addr));
}
__device__ __forceinline__ void mma_fp16(float* d, const uint32_t* a, const uint32_t* b) {
    asm volatile("mma.sync.aligned.m16n8k16.row.col.f32.f16.f16.f32 "
                 "{%0,%1,%2,%3}, {%4,%5,%6,%7}, {%8,%9}, {%0,%1,%2,%3};"
                 : "+f"(d[0]), "+f"(d[1]), "+f"(d[2]), "+f"(d[3])
                 : "r"(a[0]), "r"(a[1]), "r"(a[2]), "r"(a[3]), "r"(b[0]), "r"(b[1]));
}
__device__ __forceinline__ uint32_t swz(uint32_t off) { return off ^ ((off >> 3) & 0x70); }

// ---------------------------------------------------------------------------
// Kernel 1: blend (blocks 0..255) ∥ transpose all batches (blocks 256..4351)
//   Transpose: 32x32 tiles, vectorized: 1 float4 LDG + 1 uint2 STG per thread.
// ---------------------------------------------------------------------------
__global__ __launch_bounds__(256) void pre_kernel(const float* __restrict__ weight,
                                                  const float* __restrict__ X) {
    const int tid = threadIdx.x;
    if (blockIdx.x < 256) {
        // ---- circle-blend weights -> fp16, K-major [m][c] ----
        int t = blockIdx.x * 256 + tid;
        int o = t >> 8;
        int c = t & 255;
        const float* wp = weight + ((size_t)(o * CIN + c)) * K2;
        float w0 = wp[0], w1 = wp[1], w2 = wp[2];
        float w3 = wp[3], w4 = wp[4], w5 = wp[5];
        float w6 = wp[6], w7 = wp[7], w8 = wp[8];

        const float A  = 0.7071067811865476f;
        const float Bc = 1.0f - 0.7071067811865476f;

        float t01 = A * w0 + Bc * w1;
        float t34 = A * w3 + Bc * w4;
        float t12 = Bc * w1 + A * w2;
        float t45 = Bc * w4 + A * w5;
        float t67 = A * w6 + Bc * w7;
        float t78 = Bc * w7 + A * w8;

        float nw[K2];
        nw[0] = A * t01 + Bc * t34;  nw[1] = w1;
        nw[2] = A * t12 + Bc * t45;  nw[3] = w3;  nw[4] = w4;  nw[5] = w5;
        nw[6] = Bc * t34 + A * t67;  nw[7] = w7;
        nw[8] = Bc * t45 + A * t78;

#pragma unroll
        for (int k = 0; k < K2; k++)
            g_Wh[(size_t)(k * COUT + o) * K_GEMM + c] = __float2half_rn(nw[k]);
    } else {
        // ---- transpose x[b][c][n] -> Xt[b][n][c] in fp16, vectorized ----
        __shared__ float tle[32][33];
        int u  = blockIdx.x - 256;       // 0..4095
        int b  = u >> 10;                // 4 batches
        int r_ = u & 1023;               // 1024 tiles per batch
        int n0 = (r_ & 127) * 32;
        int c0 = (r_ >> 7) * 32;

        // load: thread (cr = tid>>3, q = tid&7) -> float4 of 4 n-values
        {
            const int cr = tid >> 3;     // c-row 0..31
            const int q  = tid & 7;      // n-quad 0..7
            float4 v = *reinterpret_cast<const float4*>(
                X + ((size_t)b * CIN + c0 + cr) * HW + n0 + q * 4);
            tle[q * 4 + 0][cr] = v.x;    // tle[n][c]
            tle[q * 4 + 1][cr] = v.y;
            tle[q * 4 + 2][cr] = v.z;
            tle[q * 4 + 3][cr] = v.w;
        }
        __syncthreads();

        // store: thread (n = tid>>3, q = tid&7) -> 4 fp16 c-values (8B)
        {
            const int n = tid >> 3;      // n-row 0..31
            const int q = tid & 7;       // c-quad 0..7
            __half2 h01 = __floats2half2_rn(tle[n][q * 4 + 0], tle[n][q * 4 + 1]);
            __half2 h23 = __floats2half2_rn(tle[n][q * 4 + 2], tle[n][q * 4 + 3]);
            uint2 pkt;
            pkt.x = *reinterpret_cast<uint32_t*>(&h01);
            pkt.y = *reinterpret_cast<uint32_t*>(&h23);
            *reinterpret_cast<uint2*>(
                g_Xh + ((size_t)b * HW + n0 + n) * CIN + c0 + q * 4) = pkt;
        }
    }
}

// ---------------------------------------------------------------------------
// Kernel 2: fp16 single-pass GEMM, 3-stage cp.async pipeline, one sync/chunk
//   G[b][k][n][o] = sum_c Xh[b][n][c] * Wh[k*256+o][c]   (stored fp16)
// ---------------------------------------------------------------------------
extern __shared__ __align__(1024) unsigned char dsmem[];

__global__ __launch_bounds__(256, 2) void gemm_fp16_kernel() {
    const int tid  = threadIdx.x;
    const int wid  = tid >> 5;
    const int lane = tid & 31;
    const int warp_m = wid >> 2;       // 0..1  (64 n-rows each)
    const int warp_n = wid & 3;        // 0..3  (32 m-cols each)

    const int b  = blockIdx.z;
    const int n0 = blockIdx.x * BM;    // n tile (A rows)
    const int m0 = blockIdx.y * BN;    // m tile (B rows)

    const uint32_t sbase = smem_u32(dsmem);

    const __half* A_g = g_Xh + ((size_t)b * HW + n0) * CIN;
    const __half* B_g = g_Wh + (size_t)m0 * K_GEMM;

    auto copy_chunk = [&](int ch) {
        const uint32_t sb = sbase + (ch % NSTAGE) * STAGE_B;
        const int k0 = ch * BK;
#pragma unroll
        for (int t = 0; t < 4; t++) {
            int u = t * 256 + tid;          // 0..1023
            int r = u >> 3;                 // row 0..127
            int q = u & 7;                  // 16B unit in row
            uint32_t doff = swz((uint32_t)(r * 128 + q * 16));
            CP16(sb + doff,          A_g + (size_t)r * CIN    + k0 + q * 8);
            CP16(sb + TILE_B + doff, B_g + (size_t)r * K_GEMM + k0 + q * 8);
        }
        CP_COMMIT();
    };

    float acc[4][4][4] = {};   // [mf][jj][reg]

    const int arow = warp_m * 64 + (lane & 15);
    const int acol = (lane & 16);
    const int nloc = ((lane >> 4) & 1) * 8 + (lane & 7);
    const int bcol = ((lane >> 3) & 1) * 16;

    copy_chunk(0);
    copy_chunk(1);

#pragma unroll
    for (int ch = 0; ch < NCHUNK; ch++) {
        if (ch < NCHUNK - 1) { CP_WAIT(1); } else { CP_WAIT(0); }
        __syncthreads();   // all warps done reading stage (ch+2)%NSTAGE (= ch-1)

        if (ch + 2 < NCHUNK) copy_chunk(ch + 2);   // overlap copy with compute

        const uint32_t sb = sbase + (ch % NSTAGE) * STAGE_B;
        const uint32_t tA = sb;
        const uint32_t tB = sb + TILE_B;

#pragma unroll
        for (int kf = 0; kf < BK / 16; kf++) {
            uint32_t af[4][4];
#pragma unroll
            for (int mf = 0; mf < 4; mf++) {
                uint32_t off = swz((uint32_t)((arow + mf * 16) * 128 + kf * 32 + acol));
                ldsm_x4(af[mf], tA + off);
            }
            uint32_t bf[4][2];
#pragma unroll
            for (int jp = 0; jp < 2; jp++) {
                uint32_t off = swz((uint32_t)((warp_n * 32 + jp * 16 + nloc) * 128 + kf * 32 + bcol));
                uint32_t rh[4];
                ldsm_x4(rh, tB + off);
                bf[2*jp][0]   = rh[0]; bf[2*jp][1]   = rh[1];
                bf[2*jp+1][0] = rh[2]; bf[2*jp+1][1] = rh[3];
            }
#pragma unroll
            for (int mf = 0; mf < 4; mf++)
#pragma unroll
                for (int jj = 0; jj < 4; jj++)
                    mma_fp16(acc[mf][jj], af[mf], bf[jj]);
        }
    }

    // ---- epilogue: rows = n, cols = o (m within fixed tap k), fp16 stores ----
    const int k_blk = m0 >> 8;          // tap index
    const int o0    = m0 & 255;         // o base (0 or 128)
    __half* Gout = g_Gh + ((size_t)(b * K2 + k_blk)) * HW * COUT;

    const int rbase = n0 + warp_m * 64 + (lane >> 2);          // n
    const int cbase = o0 + warp_n * 32 + (lane & 3) * 2;       // o
#pragma unroll
    for (int mf = 0; mf < 4; mf++) {
#pragma unroll
        for (int jj = 0; jj < 4; jj++) {
            int n = rbase + mf * 16;
            int o = cbase + jj * 8;
            *reinterpret_cast<__half2*>(&Gout[(size_t)n * COUT + o]) =
                __floats2half2_rn(acc[mf][jj][0], acc[mf][jj][1]);
            *reinterpret_cast<__half2*>(&Gout[(size_t)(n + 8) * COUT + o]) =
                __floats2half2_rn(acc[mf][jj][2], acc[mf][jj][3]);
        }
    }
}

// ---------------------------------------------------------------------------
// Kernel 3: combine — coalesced bilinear gather over fp16 G[b][k][n][o]
//   1 warp per pixel, 8 pixels per CTA; lane owns 8 o-channels (16B gathers).
// ---------------------------------------------------------------------------
__global__ __launch_bounds__(256, 6) void combine_kernel(
    const float* __restrict__ offset,
    const float* __restrict__ mask,
    const float* __restrict__ bias,
    float* __restrict__ out)
{
    __shared__ int4   s_idx[PPB][K2];
    __shared__ float4 s_cw[PPB][K2];
    __shared__ float  s_out[PPB][COUT];

    const int b    = blockIdx.y;
    const int p0   = blockIdx.x * PPB;
    const int tid  = threadIdx.x;
    const int w    = tid >> 5;
    const int lane = tid & 31;
    const int p    = p0 + w;

    if (lane < K2) {
        const int k  = lane;
        const int py = p >> 6;
        const int px = p & 63;

        float dy = offset[((b * 2 * K2) + 2 * k    ) * HW + p];
        float dx = offset[((b * 2 * K2) + 2 * k + 1) * HW + p];
        float m  = mask[(b * K2 + k) * HW + p];

        float yy = (float)(py - 1 + (k / 3)) + dy;
        float xx = (float)(px - 1 + (k % 3)) + dx;

        float y0f = floorf(yy), x0f = floorf(xx);
        float ly = yy - y0f, lx = xx - x0f;
        float hy = 1.0f - ly, hx = 1.0f - lx;
        int y0 = (int)y0f, x0 = (int)x0f;
        int y1 = y0 + 1,   x1 = x0 + 1;

        bool vy0 = (y0 >= 0) && (y0 < HDIM);
        bool vy1 = (y1 >= 0) && (y1 < HDIM);
        bool vx0 = (x0 >= 0) && (x0 < WDIM);
        bool vx1 = (x1 >= 0) && (x1 < WDIM);

        int cy0 = min(max(y0, 0), HDIM - 1);
        int cy1 = min(max(y1, 0), HDIM - 1);
        int cx0 = min(max(x0, 0), WDIM - 1);
        int cx1 = min(max(x1, 0), WDIM - 1);

        s_idx[w][k] = make_int4(cy0 * WDIM + cx0, cy0 * WDIM + cx1,
                                cy1 * WDIM + cx0, cy1 * WDIM + cx1);
        s_cw[w][k]  = make_float4((vy0 && vx0) ? hy * hx * m : 0.0f,
                                  (vy0 && vx1) ? hy * lx * m : 0.0f,
                                  (vy1 && vx0) ? ly * hx * m : 0.0f,
                                  (vy1 && vx1) ? ly * lx * m : 0.0f);
    }
    __syncwarp();

    const int o8 = lane * 8;
    float acc[8];
    {
        const float4* b4 = reinterpret_cast<const float4*>(bias + o8);
        float4 b0 = b4[0], b1 = b4[1];
        acc[0] = b0.x; acc[1] = b0.y; acc[2] = b0.z; acc[3] = b0.w;
        acc[4] = b1.x; acc[5] = b1.y; acc[6] = b1.z; acc[7] = b1.w;
    }

#pragma unroll
    for (int k = 0; k < K2; k++) {
        int4   id = s_idx[w][k];
        float4 cw = s_cw[w][k];
        const __half* base = g_Gh + ((size_t)(b * K2 + k)) * HW * COUT + o8;

        uint4 v0 = *reinterpret_cast<const uint4*>(base + (size_t)id.x * COUT);
        uint4 v1 = *reinterpret_cast<const uint4*>(base + (size_t)id.y * COUT);
        uint4 v2 = *reinterpret_cast<const uint4*>(base + (size_t)id.z * COUT);
        uint4 v3 = *reinterpret_cast<const uint4*>(base + (size_t)id.w * COUT);

        const __half2* h0 = reinterpret_cast<const __half2*>(&v0);
        const __half2* h1 = reinterpret_cast<const __half2*>(&v1);
        const __half2* h2 = reinterpret_cast<const __half2*>(&v2);
        const __half2* h3 = reinterpret_cast<const __half2*>(&v3);

#pragma unroll
        for (int j = 0; j < 4; j++) {
            float2 a = __half22float2(h0[j]);
            float2 bb = __half22float2(h1[j]);
            float2 c = __half22float2(h2[j]);
            float2 d = __half22float2(h3[j]);
            acc[2*j]   += cw.x * a.x + cw.y * bb.x + cw.z * c.x + cw.w * d.x;
            acc[2*j+1] += cw.x * a.y + cw.y * bb.y + cw.z * c.y + cw.w * d.y;
        }
    }

#pragma unroll
    for (int j = 0; j < 8; j++) s_out[w][o8 + j] = acc[j];
    __syncthreads();

    {
        const int o = tid;
        float4 r0 = make_float4(s_out[0][o], s_out[1][o], s_out[2][o], s_out[3][o]);
        float4 r1 = make_float4(s_out[4][o], s_out[5][o], s_out[6][o], s_out[7][o]);
        float* dst = out + ((size_t)(b * COUT + o)) * HW + p0;
        *reinterpret_cast<float4*>(dst)     = r0;
        *reinterpret_cast<float4*>(dst + 4) = r1;
    }
}

// ---------------------------------------------------------------------------
extern "C" void kernel_launch(void* const* d_in, const int* in_sizes, int n_in,
                              void* d_out, int out_size) {
    const float* x      = (const float*)d_in[0];   // [4,256,64,64]
    const float* offset = (const float*)d_in[1];   // [4,18,64,64]
    const float* mask   = (const float*)d_in[2];   // [4,9,64,64]
    const float* weight = (const float*)d_in[3];   // [256,256,3,3]
    const float* bias   = (const float*)d_in[4];   // [256]
    float* out = (float*)d_out;                    // [4,256,64,64]

    static bool attr_set = false;
    if (!attr_set) {
        cudaFuncSetAttribute(gemm_fp16_kernel,
                             cudaFuncAttributeMaxDynamicSharedMemorySize, SMEM_DYN);
        attr_set = true;
    }

    pre_kernel<<<256 + BATCH * 1024, 256>>>(weight, x);
    gemm_fp16_kernel<<<dim3(HW / BM, M_GEMM / BN, BATCH), 256, SMEM_DYN>>>();
    combine_kernel<<<dim3(HW / PPB, BATCH), 256>>>(offset, mask, bias, out);
}